// round 6
// baseline (speedup 1.0000x reference)
#include <cuda_runtime.h>
#include <cstdint>

// ---------------------------------------------------------------------------
// Decoder: emb gather + concat -> LSTM x2 (persistent) -> FC
// B=64, T=32, E=H=512, V=32000.  GEMMs: HMMA tf32, cp.async 4-stage.
// All GEMM operands pre-rounded to tf32-RNA by producers, so the raw-bit
// cp.async path is exact (truncation of already-rounded values is a no-op).
// ---------------------------------------------------------------------------
#define B_  64
#define T_  32
#define E_  512
#define H_  512
#define V_  32000
#define M_  (B_ * T_)    // 2048
#define G4_ (4 * H_)     // 2048
#define NB_ 64           // persistent blocks for LSTM

__device__ float    g_x0[M_ * E_];
__device__ float    g_xp[M_ * G4_];
__device__ float    g_hseq[M_ * H_];
__device__ uint32_t g_hf0[B_ * H_];
__device__ uint32_t g_hf1[B_ * H_];
__device__ float    g_wih0[G4_ * E_];     // 4 MB  tf32-rounded W_ih0
__device__ float    g_wih1[G4_ * H_];     // 4 MB  tf32-rounded W_ih1
__device__ float    g_fcw[V_ * H_];       // 64 MB tf32-rounded fc_W
__device__ unsigned g_cnt;
__device__ unsigned g_sense;

// ---------------------------------------------------------------------------
__device__ __forceinline__ uint32_t f2tf32(float x) {
    uint32_t r;
    asm("cvt.rna.tf32.f32 %0, %1;" : "=r"(r) : "f"(x));
    return r;
}
__device__ __forceinline__ float rna_tf32(float x) {
    return __uint_as_float(f2tf32(x));
}

__device__ __forceinline__ void mma_tf32(float (&c)[4], const uint32_t (&a)[4],
                                         const uint32_t (&b)[2]) {
    asm volatile(
        "mma.sync.aligned.m16n8k8.row.col.f32.tf32.tf32.f32 "
        "{%0,%1,%2,%3}, {%4,%5,%6,%7}, {%8,%9}, {%0,%1,%2,%3};\n"
        : "+f"(c[0]), "+f"(c[1]), "+f"(c[2]), "+f"(c[3])
        : "r"(a[0]), "r"(a[1]), "r"(a[2]), "r"(a[3]), "r"(b[0]), "r"(b[1]));
}

__device__ __forceinline__ unsigned atom_add_rel(unsigned* p) {
    unsigned old;
    asm volatile("atom.release.gpu.global.add.u32 %0, [%1], 1;"
                 : "=r"(old) : "l"(p) : "memory");
    return old;
}
__device__ __forceinline__ void st_rel(unsigned* p, unsigned v) {
    asm volatile("st.release.gpu.global.u32 [%0], %1;" :: "l"(p), "r"(v)
                 : "memory");
}
__device__ __forceinline__ unsigned ld_acq(unsigned* p) {
    unsigned v;
    asm volatile("ld.acquire.gpu.global.u32 %0, [%1];" : "=r"(v) : "l"(p)
                 : "memory");
    return v;
}

__device__ __forceinline__ uint32_t smem_u32(const void* p) {
    uint32_t a;
    asm("{ .reg .u64 t; cvta.to.shared.u64 t, %1; cvt.u32.u64 %0, t; }"
        : "=r"(a) : "l"(p));
    return a;
}

__device__ __forceinline__ void cp16(uint32_t dst, const void* src) {
    asm volatile("cp.async.cg.shared.global [%0], [%1], 16;\n"
                 :: "r"(dst), "l"(src));
}

// ---------------------------------------------------------------------------
// Pre-round weights to tf32 RNA (vectorized elementwise copy).
// ---------------------------------------------------------------------------
__global__ void round_w(const float* __restrict__ src, float* __restrict__ dst,
                        int n4) {
    int i = blockIdx.x * blockDim.x + threadIdx.x;
    if (i >= n4) return;
    float4 v = *(const float4*)(src + (size_t)i * 4);
    v.x = rna_tf32(v.x); v.y = rna_tf32(v.y);
    v.z = rna_tf32(v.z); v.w = rna_tf32(v.w);
    *(float4*)(dst + (size_t)i * 4) = v;
}

// ---------------------------------------------------------------------------
__global__ void build_x0(const int* __restrict__ sentence,
                         const float* __restrict__ features,
                         const float* __restrict__ emb,
                         float* __restrict__ x0) {
    int i4 = blockIdx.x * blockDim.x + threadIdx.x;
    if (i4 >= M_ * (E_ / 4)) return;
    int m  = i4 >> 7;
    int e4 = (i4 & 127) * 4;
    int b  = m >> 5;
    int t  = m & 31;
    float4 v;
    if (t == 0) {
        v = *(const float4*)&features[b * E_ + e4];
    } else {
        int tok = sentence[b * T_ + (t - 1)];
        v = *(const float4*)&emb[tok * E_ + e4];
    }
    v.x = rna_tf32(v.x); v.y = rna_tf32(v.y);
    v.z = rna_tf32(v.z); v.w = rna_tf32(v.w);
    *(float4*)&x0[m * E_ + e4] = v;
}

__global__ void reset_bar() { g_cnt = 0; g_sense = 0; }

// ---------------------------------------------------------------------------
// tf32 GEMM, cp.async 4-stage pipeline, BM=128 BN=256 BK=32, 256 threads.
// Warp tile 64x64 (8 warps: 2m x 4n). Operands pre-rounded tf32 (raw bits).
// K must be 512 (KI=16).  C[M,N] = A[M,K]*Bm[N,K]^T + bias1 (+bias2).
// MODE 0: row-major C.  MODE 1: out[b,n,t], m = b*32+t.
// ---------------------------------------------------------------------------
#define GLDSM 36
#define GSTGB ((128 + 256) * GLDSM * 4)

template <int MODE>
__global__ void __launch_bounds__(256)
gemm2(const float* __restrict__ A, const float* __restrict__ Bm,
      const float* __restrict__ bias1, const float* __restrict__ bias2,
      float* __restrict__ C, int M, int N, int K) {
    extern __shared__ uint8_t dsm[];
    const uint32_t base = smem_u32(dsm);

    const int tid  = threadIdx.x;
    const int lane = tid & 31;
    const int warp = tid >> 5;
    const int wm = (warp & 1) * 64;
    const int wn = (warp >> 1) * 64;
    const int m0 = blockIdx.y * 128;
    const int n0 = blockIdx.x * 256;

    float acc[4][8][4];
#pragma unroll
    for (int mt = 0; mt < 4; mt++)
#pragma unroll
        for (int nt = 0; nt < 8; nt++)
#pragma unroll
            for (int i = 0; i < 4; i++) acc[mt][nt][i] = 0.f;

    auto issue = [&](int s) {
        uint32_t sa = base + (s & 3) * GSTGB;
        uint32_t sb = sa + 128 * GLDSM * 4;
        const float* ap = A + (size_t)m0 * K + s * 32;
        const float* wp = Bm + (size_t)n0 * K + s * 32;
#pragma unroll
        for (int i = 0; i < 4; i++) {           // A: 128 rows x 8 chunks
            int c = i * 256 + tid;
            int row = c >> 3, kk = c & 7;
            cp16(sa + (uint32_t)(row * GLDSM + kk * 4) * 4,
                 ap + (size_t)row * K + kk * 4);
        }
#pragma unroll
        for (int i = 0; i < 8; i++) {           // B: 256 rows x 8 chunks
            int c = i * 256 + tid;
            int row = c >> 3, kk = c & 7;
            cp16(sb + (uint32_t)(row * GLDSM + kk * 4) * 4,
                 wp + (size_t)row * K + kk * 4);
        }
    };

    // prologue: stages 0..2
#pragma unroll
    for (int s = 0; s < 3; s++) {
        issue(s);
        asm volatile("cp.async.commit_group;" ::: "memory");
    }

    for (int k = 0; k < 16; k++) {
        if (k <= 13)      asm volatile("cp.async.wait_group 2;" ::: "memory");
        else if (k == 14) asm volatile("cp.async.wait_group 1;" ::: "memory");
        else              asm volatile("cp.async.wait_group 0;" ::: "memory");
        __syncthreads();
        if (k + 3 < 16) {
            issue(k + 3);
            asm volatile("cp.async.commit_group;" ::: "memory");
        }

        const uint32_t* As = (const uint32_t*)(dsm + (size_t)(k & 3) * GSTGB);
        const uint32_t* Bs = As + 128 * GLDSM;
#pragma unroll
        for (int ks = 0; ks < 4; ks++) {
            int kc = ks * 8 + (lane & 3);
            uint32_t bf[8][2];
#pragma unroll
            for (int nt = 0; nt < 8; nt++) {
                int nr = wn + nt * 8 + (lane >> 2);
                bf[nt][0] = Bs[nr * GLDSM + kc];
                bf[nt][1] = Bs[nr * GLDSM + kc + 4];
            }
#pragma unroll
            for (int mt = 0; mt < 4; mt++) {
                int r = wm + mt * 16 + (lane >> 2);
                uint32_t af[4];
                af[0] = As[r * GLDSM + kc];
                af[1] = As[(r + 8) * GLDSM + kc];
                af[2] = As[r * GLDSM + kc + 4];
                af[3] = As[(r + 8) * GLDSM + kc + 4];
#pragma unroll
                for (int nt = 0; nt < 8; nt++)
                    mma_tf32(acc[mt][nt], af, bf[nt]);
            }
        }
    }

    // epilogue
#pragma unroll
    for (int nt = 0; nt < 8; nt++) {
        int cn  = n0 + wn + nt * 8 + (lane & 3) * 2;
        float bv0 = bias1[cn];
        float bv1 = bias1[cn + 1];
        if (MODE == 0 && bias2) { bv0 += bias2[cn]; bv1 += bias2[cn + 1]; }
#pragma unroll
        for (int mt = 0; mt < 4; mt++) {
            int r = m0 + wm + mt * 16 + (lane >> 2);
            float v0 = acc[mt][nt][0] + bv0;
            float v1 = acc[mt][nt][1] + bv1;
            float v2 = acc[mt][nt][2] + bv0;
            float v3 = acc[mt][nt][3] + bv1;
            if (MODE == 0) {
                C[(size_t)r * N + cn]           = v0;
                C[(size_t)r * N + cn + 1]       = v1;
                C[(size_t)(r + 8) * N + cn]     = v2;
                C[(size_t)(r + 8) * N + cn + 1] = v3;
            } else {
                int b1 = r >> 5, t1 = r & 31;
                int b2 = (r + 8) >> 5, t2 = (r + 8) & 31;
                size_t base1 = (size_t)b1 * N * T_ + t1;
                size_t base2 = (size_t)b2 * N * T_ + t2;
                C[base1 + (size_t)cn * T_]       = v0;
                C[base1 + (size_t)(cn + 1) * T_] = v1;
                C[base2 + (size_t)cn * T_]       = v2;
                C[base2 + (size_t)(cn + 1) * T_] = v3;
            }
        }
    }
}

// ---------------------------------------------------------------------------
// Persistent LSTM layer (round-3 version; hseq stores now tf32-rounded).
// ---------------------------------------------------------------------------
__global__ void __launch_bounds__(256, 1)
lstm_layer(const float* __restrict__ xp, const float* __restrict__ Whh,
           uint32_t* __restrict__ hf0, uint32_t* __restrict__ hf1,
           float* __restrict__ hseq) {
    extern __shared__ uint32_t smu[];
    uint32_t* hsf = smu;                    // 32768 u32 = 128KB
    float*    red = (float*)(smu + 32768);  // 16384 f = 64KB

    const int tid  = threadIdx.x;
    const int lane = tid & 31;
    const int w    = tid >> 5;
    const int gid  = lane >> 2;
    const int tig  = lane & 3;
    const int j0   = blockIdx.x * 8;
    const int kt_o = blockIdx.x;

    uint32_t bfr[4][8][2];
#pragma unroll
    for (int nt = 0; nt < 4; nt++)
#pragma unroll
        for (int ktl = 0; ktl < 8; ktl++) {
            int k   = w * 64 + ktl * 8 + tig;
            int row = nt * H_ + j0 + gid;
            bfr[nt][ktl][0] = f2tf32(Whh[(size_t)row * H_ + k]);
            bfr[nt][ktl][1] = f2tf32(Whh[(size_t)row * H_ + k + 4]);
        }

#pragma unroll 4
    for (int i = tid; i < 8192; i += 256)
        *(uint4*)&hsf[i * 4] = make_uint4(0u, 0u, 0u, 0u);

    const int jj = tid & 7;
    const int bq = tid >> 3;
    float creg0 = 0.f, creg1 = 0.f;

    for (int t = 0; t < T_; t++) {
        float xpr[2][4];
#pragma unroll
        for (int half = 0; half < 2; half++) {
            int b = bq + half * 32;
#pragma unroll
            for (int g = 0; g < 4; g++)
                xpr[half][g] = xp[(size_t)(b * T_ + t) * G4_ + g * H_ + j0 + jj];
        }

        if (t > 0) {
            if (tid == 0) {
                while (ld_acq(&g_sense) < (unsigned)t) { }
            }
            __syncthreads();
            const uint4* src = (const uint4*)((t & 1) ? hf0 : hf1);
#pragma unroll
            for (int it = 0; it < 32; it++) {
                int idx = it * 256 + tid;
                uint4 v = __ldcg(src + idx);
                *(uint4*)&hsf[idx * 4] = v;
            }
        }
        __syncthreads();

        float acc[4][4][4];
#pragma unroll
        for (int mt = 0; mt < 4; mt++)
#pragma unroll
            for (int nt = 0; nt < 4; nt++)
#pragma unroll
                for (int i = 0; i < 4; i++) acc[mt][nt][i] = 0.f;

#pragma unroll
        for (int ktl = 0; ktl < 8; ktl++) {
            int ktg = w * 8 + ktl;
            uint32_t a[4][4];
#pragma unroll
            for (int mt = 0; mt < 4; mt++) {
                uint4 av = *(const uint4*)&hsf[(((mt * 64 + ktg) * 32) + lane) * 4];
                a[mt][0] = av.x; a[mt][1] = av.y; a[mt][2] = av.z; a[mt][3] = av.w;
            }
#pragma unroll
            for (int mt = 0; mt < 4; mt++)
#pragma unroll
                for (int nt = 0; nt < 4; nt++)
                    mma_tf32(acc[mt][nt], a[mt], bfr[nt][ktl]);
        }

#pragma unroll
        for (int mt = 0; mt < 4; mt++)
#pragma unroll
            for (int nt = 0; nt < 4; nt++)
                *(float4*)&red[(((w * 4 + mt) * 4 + nt) << 7) + lane * 4] =
                    make_float4(acc[mt][nt][0], acc[mt][nt][1],
                                acc[mt][nt][2], acc[mt][nt][3]);
        __syncthreads();

        uint32_t* hdst = (t & 1) ? hf1 : hf0;
        const int e   = jj & 3;
        const int qlo = jj >> 2;
#pragma unroll
        for (int half = 0; half < 2; half++) {
            int b     = bq + half * 32;
            int row_t = b & 15;
            int mt    = b >> 4;
            int pos   = (((row_t & 7) * 4 + (jj >> 1)) << 2) + (jj & 1) +
                        ((row_t >> 3) << 1);
            float gv[4];
#pragma unroll
            for (int g = 0; g < 4; g++) {
                float s = xpr[half][g];
#pragma unroll
                for (int ww = 0; ww < 8; ww++)
                    s += red[(((ww * 4 + mt) * 4 + g) << 7) + pos];
                gv[g] = s;
            }
            float ig = 1.f / (1.f + __expf(-gv[0]));
            float fg = 1.f / (1.f + __expf(-gv[1]));
            float gg = tanhf(gv[2]);
            float og = 1.f / (1.f + __expf(-gv[3]));
            float cold = half ? creg1 : creg0;
            float cn = fg * cold + ig * gg;
            if (half) creg1 = cn; else creg0 = cn;
            float hn = og * tanhf(cn);
            uint32_t hbits = f2tf32(hn);
            int lane_p = (b & 7) * 4 + e;
            int ai     = ((b >> 3) & 1) | (qlo << 1);
            hdst[((mt * 64 + kt_o) * 32 + lane_p) * 4 + ai] = hbits;
            // tf32-rounded so downstream raw-bit GEMMs are exact RNA
            hseq[(size_t)(b * T_ + t) * H_ + j0 + jj] = __uint_as_float(hbits);
        }

        if (t < T_ - 1) {
            __syncthreads();
            if (tid == 0) {
                unsigned old = atom_add_rel(&g_cnt);
                if (old == (unsigned)(NB_ * (t + 1) - 1))
                    st_rel(&g_sense, (unsigned)(t + 1));
            }
        }
    }
}

// ---------------------------------------------------------------------------
extern "C" void kernel_launch(void* const* d_in, const int* in_sizes, int n_in,
                              void* d_out, int out_size) {
    (void)in_sizes; (void)n_in; (void)out_size;
    const int*   sentence = (const int*)d_in[0];
    const float* features = (const float*)d_in[1];
    const float* emb   = (const float*)d_in[3];
    const float* W_ih0 = (const float*)d_in[4];
    const float* W_hh0 = (const float*)d_in[5];
    const float* b_ih0 = (const float*)d_in[6];
    const float* b_hh0 = (const float*)d_in[7];
    const float* W_ih1 = (const float*)d_in[8];
    const float* W_hh1 = (const float*)d_in[9];
    const float* b_ih1 = (const float*)d_in[10];
    const float* b_hh1 = (const float*)d_in[11];
    const float* fc_W  = (const float*)d_in[12];
    const float* fc_b  = (const float*)d_in[13];
    float* out = (float*)d_out;

    float *x0, *xp, *hseq, *wih0, *wih1, *fcw;
    uint32_t *hf0, *hf1;
    cudaGetSymbolAddress((void**)&x0, g_x0);
    cudaGetSymbolAddress((void**)&xp, g_xp);
    cudaGetSymbolAddress((void**)&hseq, g_hseq);
    cudaGetSymbolAddress((void**)&hf0, g_hf0);
    cudaGetSymbolAddress((void**)&hf1, g_hf1);
    cudaGetSymbolAddress((void**)&wih0, g_wih0);
    cudaGetSymbolAddress((void**)&wih1, g_wih1);
    cudaGetSymbolAddress((void**)&fcw, g_fcw);

    cudaFuncSetAttribute(lstm_layer,
                         cudaFuncAttributeMaxDynamicSharedMemorySize, 196608);
    cudaFuncSetAttribute(gemm2<0>,
                         cudaFuncAttributeMaxDynamicSharedMemorySize, 4 * GSTGB);
    cudaFuncSetAttribute(gemm2<1>,
                         cudaFuncAttributeMaxDynamicSharedMemorySize, 4 * GSTGB);

    // pre-round weights to tf32 RNA (raw-bit GEMM path then exact)
    round_w<<<(G4_ * E_ / 4 + 255) / 256, 256>>>(W_ih0, wih0, G4_ * E_ / 4);
    round_w<<<(G4_ * H_ / 4 + 255) / 256, 256>>>(W_ih1, wih1, G4_ * H_ / 4);
    round_w<<<(V_ * H_ / 4 + 255) / 256, 256>>>(fc_W, fcw, V_ * H_ / 4);

    build_x0<<<(M_ * (E_ / 4) + 255) / 256, 256>>>(sentence, features, emb, x0);

    gemm2<0><<<dim3(G4_ / 256, M_ / 128), 256, 4 * GSTGB>>>(
        x0, wih0, b_ih0, b_hh0, xp, M_, G4_, E_);
    reset_bar<<<1, 1>>>();
    lstm_layer<<<NB_, 256, 196608>>>(xp, W_hh0, hf0, hf1, hseq);

    gemm2<0><<<dim3(G4_ / 256, M_ / 128), 256, 4 * GSTGB>>>(
        hseq, wih1, b_ih1, b_hh1, xp, M_, G4_, H_);
    reset_bar<<<1, 1>>>();
    lstm_layer<<<NB_, 256, 196608>>>(xp, W_hh1, hf0, hf1, hseq);

    gemm2<1><<<dim3(V_ / 256, M_ / 128), 256, 4 * GSTGB>>>(
        hseq, fcw, fc_b, nullptr, out, M_, V_, H_);
}

// round 7
// speedup vs baseline: 1.2337x; 1.2337x over previous
#include <cuda_runtime.h>
#include <cuda_fp16.h>
#include <cstdint>

// ---------------------------------------------------------------------------
// Decoder: emb gather + concat -> LSTM x2 (persistent tf32) -> FC
// B=64, T=32, E=H=512, V=32000.
// GEMMs: fp16 HMMA m16n8k16 (same 10-bit mantissa as tf32 -> same accuracy,
// full tensor rate), cp.async 4-stage, fp32 accumulate.
// ---------------------------------------------------------------------------
#define B_  64
#define T_  32
#define E_  512
#define H_  512
#define V_  32000
#define M_  (B_ * T_)    // 2048
#define G4_ (4 * H_)     // 2048
#define NB_ 64           // persistent blocks for LSTM

__device__ __half   g_x0[M_ * E_];        // fp16 concat input
__device__ float    g_xp[M_ * G4_];       // fp32 gate pre-activations
__device__ __half   g_hseq[M_ * H_];      // fp16 h sequence (GEMM A operand)
__device__ uint32_t g_hf0[B_ * H_];       // tf32 frag-shuffled h (LSTM internal)
__device__ uint32_t g_hf1[B_ * H_];
__device__ __half   g_wih0[G4_ * E_];     // fp16 weights
__device__ __half   g_wih1[G4_ * H_];
__device__ __half   g_fcw[V_ * H_];       // 32 MB (fits L2)
__device__ unsigned g_cnt;
__device__ unsigned g_sense;

// ---------------------------------------------------------------------------
__device__ __forceinline__ uint32_t f2tf32(float x) {
    uint32_t r;
    asm("cvt.rna.tf32.f32 %0, %1;" : "=r"(r) : "f"(x));
    return r;
}

__device__ __forceinline__ void mma_tf32(float (&c)[4], const uint32_t (&a)[4],
                                         const uint32_t (&b)[2]) {
    asm volatile(
        "mma.sync.aligned.m16n8k8.row.col.f32.tf32.tf32.f32 "
        "{%0,%1,%2,%3}, {%4,%5,%6,%7}, {%8,%9}, {%0,%1,%2,%3};\n"
        : "+f"(c[0]), "+f"(c[1]), "+f"(c[2]), "+f"(c[3])
        : "r"(a[0]), "r"(a[1]), "r"(a[2]), "r"(a[3]), "r"(b[0]), "r"(b[1]));
}

__device__ __forceinline__ void mma_f16(float (&c)[4], const uint32_t (&a)[4],
                                        const uint32_t (&b)[2]) {
    asm volatile(
        "mma.sync.aligned.m16n8k16.row.col.f32.f16.f16.f32 "
        "{%0,%1,%2,%3}, {%4,%5,%6,%7}, {%8,%9}, {%0,%1,%2,%3};\n"
        : "+f"(c[0]), "+f"(c[1]), "+f"(c[2]), "+f"(c[3])
        : "r"(a[0]), "r"(a[1]), "r"(a[2]), "r"(a[3]), "r"(b[0]), "r"(b[1]));
}

__device__ __forceinline__ unsigned atom_add_rel(unsigned* p) {
    unsigned old;
    asm volatile("atom.release.gpu.global.add.u32 %0, [%1], 1;"
                 : "=r"(old) : "l"(p) : "memory");
    return old;
}
__device__ __forceinline__ void st_rel(unsigned* p, unsigned v) {
    asm volatile("st.release.gpu.global.u32 [%0], %1;" :: "l"(p), "r"(v)
                 : "memory");
}
__device__ __forceinline__ unsigned ld_acq(unsigned* p) {
    unsigned v;
    asm volatile("ld.acquire.gpu.global.u32 %0, [%1];" : "=r"(v) : "l"(p)
                 : "memory");
    return v;
}

__device__ __forceinline__ uint32_t smem_u32(const void* p) {
    uint32_t a;
    asm("{ .reg .u64 t; cvta.to.shared.u64 t, %1; cvt.u32.u64 %0, t; }"
        : "=r"(a) : "l"(p));
    return a;
}

__device__ __forceinline__ void cp16(uint32_t dst, const void* src) {
    asm volatile("cp.async.cg.shared.global [%0], [%1], 16;\n"
                 :: "r"(dst), "l"(src));
}

// ---------------------------------------------------------------------------
// fp32 -> fp16 weight conversion (one thread = 4 elements)
// ---------------------------------------------------------------------------
__global__ void to_half(const float* __restrict__ src, __half* __restrict__ dst,
                        int n4) {
    int i = blockIdx.x * blockDim.x + threadIdx.x;
    if (i >= n4) return;
    float4 v = *(const float4*)(src + (size_t)i * 4);
    __half2 h0 = __floats2half2_rn(v.x, v.y);
    __half2 h1 = __floats2half2_rn(v.z, v.w);
    uint2 u;
    u.x = *(uint32_t*)&h0;
    u.y = *(uint32_t*)&h1;
    *(uint2*)(dst + (size_t)i * 4) = u;
}

// ---------------------------------------------------------------------------
__global__ void build_x0(const int* __restrict__ sentence,
                         const float* __restrict__ features,
                         const float* __restrict__ emb,
                         __half* __restrict__ x0) {
    int i4 = blockIdx.x * blockDim.x + threadIdx.x;
    if (i4 >= M_ * (E_ / 4)) return;
    int m  = i4 >> 7;
    int e4 = (i4 & 127) * 4;
    int b  = m >> 5;
    int t  = m & 31;
    float4 v;
    if (t == 0) {
        v = *(const float4*)&features[b * E_ + e4];
    } else {
        int tok = sentence[b * T_ + (t - 1)];
        v = *(const float4*)&emb[tok * E_ + e4];
    }
    __half2 h0 = __floats2half2_rn(v.x, v.y);
    __half2 h1 = __floats2half2_rn(v.z, v.w);
    uint2 u;
    u.x = *(uint32_t*)&h0;
    u.y = *(uint32_t*)&h1;
    *(uint2*)(x0 + (size_t)m * E_ + e4) = u;
}

__global__ void reset_bar() { g_cnt = 0; g_sense = 0; }

// ---------------------------------------------------------------------------
// fp16 GEMM, cp.async 4-stage, BM=128 BN=256 BK=32(halves), 256 threads.
// Warp tile 64x64 (8 warps: 2m x 4n), mma m16n8k16, fp32 accumulate.
// K = 512.  C[M,N] = A[M,K]*Bm[N,K]^T + bias1 (+bias2).
// MODE 0: row-major fp32 C.  MODE 1: out[b,n,t], m = b*32+t.
// smem row = 32 halves + 8 pad = 80B (fragment loads bank-conflict-free,
// 16B-aligned for cp.async). Stage = (128+256)*80 = 30720B; x4 = 122880B.
// ---------------------------------------------------------------------------
#define HLDW 20                      // u32 words per smem row
#define HSTG ((128 + 256) * HLDW * 4)

template <int MODE>
__global__ void __launch_bounds__(256)
gemm2h(const __half* __restrict__ A, const __half* __restrict__ Bm,
       const float* __restrict__ bias1, const float* __restrict__ bias2,
       float* __restrict__ C, int M, int N, int K) {
    extern __shared__ uint8_t dsm[];
    const uint32_t base = smem_u32(dsm);

    const int tid  = threadIdx.x;
    const int lane = tid & 31;
    const int warp = tid >> 5;
    const int wm = (warp & 1) * 64;
    const int wn = (warp >> 1) * 64;
    const int m0 = blockIdx.y * 128;
    const int n0 = blockIdx.x * 256;

    float acc[4][8][4];
#pragma unroll
    for (int mt = 0; mt < 4; mt++)
#pragma unroll
        for (int nt = 0; nt < 8; nt++)
#pragma unroll
            for (int i = 0; i < 4; i++) acc[mt][nt][i] = 0.f;

    auto issue = [&](int s) {
        uint32_t sa = base + (s & 3) * HSTG;
        uint32_t sb = sa + 128 * HLDW * 4;
        const __half* ap = A + (size_t)m0 * K + s * 32;
        const __half* wp = Bm + (size_t)n0 * K + s * 32;
#pragma unroll
        for (int i = 0; i < 2; i++) {           // A: 128 rows x 4 chunks
            int c = i * 256 + tid;
            int row = c >> 2, kk = c & 3;
            cp16(sa + (uint32_t)(row * 80 + kk * 16),
                 ap + (size_t)row * K + kk * 8);
        }
#pragma unroll
        for (int i = 0; i < 4; i++) {           // B: 256 rows x 4 chunks
            int c = i * 256 + tid;
            int row = c >> 2, kk = c & 3;
            cp16(sb + (uint32_t)(row * 80 + kk * 16),
                 wp + (size_t)row * K + kk * 8);
        }
    };

    // prologue: stages 0..2
#pragma unroll
    for (int s = 0; s < 3; s++) {
        issue(s);
        asm volatile("cp.async.commit_group;" ::: "memory");
    }

    for (int k = 0; k < 16; k++) {
        if (k <= 13)      asm volatile("cp.async.wait_group 2;" ::: "memory");
        else if (k == 14) asm volatile("cp.async.wait_group 1;" ::: "memory");
        else              asm volatile("cp.async.wait_group 0;" ::: "memory");
        __syncthreads();
        if (k + 3 < 16) {
            issue(k + 3);
            asm volatile("cp.async.commit_group;" ::: "memory");
        }

        const uint32_t* As = (const uint32_t*)(dsm + (size_t)(k & 3) * HSTG);
        const uint32_t* Bs = As + 128 * HLDW;
#pragma unroll
        for (int ks = 0; ks < 2; ks++) {          // two k16 sub-steps
            int kc = ks * 8 + (lane & 3);
            uint32_t bf[8][2];
#pragma unroll
            for (int nt = 0; nt < 8; nt++) {
                int nr = wn + nt * 8 + (lane >> 2);
                bf[nt][0] = Bs[nr * HLDW + kc];
                bf[nt][1] = Bs[nr * HLDW + kc + 4];
            }
#pragma unroll
            for (int mt = 0; mt < 4; mt++) {
                int r = wm + mt * 16 + (lane >> 2);
                uint32_t af[4];
                af[0] = As[r * HLDW + kc];
                af[1] = As[(r + 8) * HLDW + kc];
                af[2] = As[r * HLDW + kc + 4];
                af[3] = As[(r + 8) * HLDW + kc + 4];
#pragma unroll
                for (int nt = 0; nt < 8; nt++)
                    mma_f16(acc[mt][nt], af, bf[nt]);
            }
        }
    }

    // epilogue
#pragma unroll
    for (int nt = 0; nt < 8; nt++) {
        int cn  = n0 + wn + nt * 8 + (lane & 3) * 2;
        float bv0 = bias1[cn];
        float bv1 = bias1[cn + 1];
        if (MODE == 0 && bias2) { bv0 += bias2[cn]; bv1 += bias2[cn + 1]; }
#pragma unroll
        for (int mt = 0; mt < 4; mt++) {
            int r = m0 + wm + mt * 16 + (lane >> 2);
            float v0 = acc[mt][nt][0] + bv0;
            float v1 = acc[mt][nt][1] + bv1;
            float v2 = acc[mt][nt][2] + bv0;
            float v3 = acc[mt][nt][3] + bv1;
            if (MODE == 0) {
                C[(size_t)r * N + cn]           = v0;
                C[(size_t)r * N + cn + 1]       = v1;
                C[(size_t)(r + 8) * N + cn]     = v2;
                C[(size_t)(r + 8) * N + cn + 1] = v3;
            } else {
                int b1 = r >> 5, t1 = r & 31;
                int b2 = (r + 8) >> 5, t2 = (r + 8) & 31;
                size_t base1 = (size_t)b1 * N * T_ + t1;
                size_t base2 = (size_t)b2 * N * T_ + t2;
                C[base1 + (size_t)cn * T_]       = v0;
                C[base1 + (size_t)(cn + 1) * T_] = v1;
                C[base2 + (size_t)cn * T_]       = v2;
                C[base2 + (size_t)(cn + 1) * T_] = v3;
            }
        }
    }
}

// ---------------------------------------------------------------------------
// Persistent LSTM layer (proven tf32 internals; hseq stored fp16 now —
// identical 10-bit mantissa to the previous tf32-rounded store).
// ---------------------------------------------------------------------------
__global__ void __launch_bounds__(256, 1)
lstm_layer(const float* __restrict__ xp, const float* __restrict__ Whh,
           uint32_t* __restrict__ hf0, uint32_t* __restrict__ hf1,
           __half* __restrict__ hseq) {
    extern __shared__ uint32_t smu[];
    uint32_t* hsf = smu;                    // 32768 u32 = 128KB
    float*    red = (float*)(smu + 32768);  // 16384 f = 64KB

    const int tid  = threadIdx.x;
    const int lane = tid & 31;
    const int w    = tid >> 5;
    const int gid  = lane >> 2;
    const int tig  = lane & 3;
    const int j0   = blockIdx.x * 8;
    const int kt_o = blockIdx.x;

    uint32_t bfr[4][8][2];
#pragma unroll
    for (int nt = 0; nt < 4; nt++)
#pragma unroll
        for (int ktl = 0; ktl < 8; ktl++) {
            int k   = w * 64 + ktl * 8 + tig;
            int row = nt * H_ + j0 + gid;
            bfr[nt][ktl][0] = f2tf32(Whh[(size_t)row * H_ + k]);
            bfr[nt][ktl][1] = f2tf32(Whh[(size_t)row * H_ + k + 4]);
        }

#pragma unroll 4
    for (int i = tid; i < 8192; i += 256)
        *(uint4*)&hsf[i * 4] = make_uint4(0u, 0u, 0u, 0u);

    const int jj = tid & 7;
    const int bq = tid >> 3;
    float creg0 = 0.f, creg1 = 0.f;

    for (int t = 0; t < T_; t++) {
        float xpr[2][4];
#pragma unroll
        for (int half = 0; half < 2; half++) {
            int b = bq + half * 32;
#pragma unroll
            for (int g = 0; g < 4; g++)
                xpr[half][g] = xp[(size_t)(b * T_ + t) * G4_ + g * H_ + j0 + jj];
        }

        if (t > 0) {
            if (tid == 0) {
                while (ld_acq(&g_sense) < (unsigned)t) { }
            }
            __syncthreads();
            const uint4* src = (const uint4*)((t & 1) ? hf0 : hf1);
#pragma unroll
            for (int it = 0; it < 32; it++) {
                int idx = it * 256 + tid;
                uint4 v = __ldcg(src + idx);
                *(uint4*)&hsf[idx * 4] = v;
            }
        }
        __syncthreads();

        float acc[4][4][4];
#pragma unroll
        for (int mt = 0; mt < 4; mt++)
#pragma unroll
            for (int nt = 0; nt < 4; nt++)
#pragma unroll
                for (int i = 0; i < 4; i++) acc[mt][nt][i] = 0.f;

#pragma unroll
        for (int ktl = 0; ktl < 8; ktl++) {
            int ktg = w * 8 + ktl;
            uint32_t a[4][4];
#pragma unroll
            for (int mt = 0; mt < 4; mt++) {
                uint4 av = *(const uint4*)&hsf[(((mt * 64 + ktg) * 32) + lane) * 4];
                a[mt][0] = av.x; a[mt][1] = av.y; a[mt][2] = av.z; a[mt][3] = av.w;
            }
#pragma unroll
            for (int mt = 0; mt < 4; mt++)
#pragma unroll
                for (int nt = 0; nt < 4; nt++)
                    mma_tf32(acc[mt][nt], a[mt], bfr[nt][ktl]);
        }

#pragma unroll
        for (int mt = 0; mt < 4; mt++)
#pragma unroll
            for (int nt = 0; nt < 4; nt++)
                *(float4*)&red[(((w * 4 + mt) * 4 + nt) << 7) + lane * 4] =
                    make_float4(acc[mt][nt][0], acc[mt][nt][1],
                                acc[mt][nt][2], acc[mt][nt][3]);
        __syncthreads();

        uint32_t* hdst = (t & 1) ? hf1 : hf0;
        const int e   = jj & 3;
        const int qlo = jj >> 2;
#pragma unroll
        for (int half = 0; half < 2; half++) {
            int b     = bq + half * 32;
            int row_t = b & 15;
            int mt    = b >> 4;
            int pos   = (((row_t & 7) * 4 + (jj >> 1)) << 2) + (jj & 1) +
                        ((row_t >> 3) << 1);
            float gv[4];
#pragma unroll
            for (int g = 0; g < 4; g++) {
                float s = xpr[half][g];
#pragma unroll
                for (int ww = 0; ww < 8; ww++)
                    s += red[(((ww * 4 + mt) * 4 + g) << 7) + pos];
                gv[g] = s;
            }
            float ig = 1.f / (1.f + __expf(-gv[0]));
            float fg = 1.f / (1.f + __expf(-gv[1]));
            float gg = tanhf(gv[2]);
            float og = 1.f / (1.f + __expf(-gv[3]));
            float cold = half ? creg1 : creg0;
            float cn = fg * cold + ig * gg;
            if (half) creg1 = cn; else creg0 = cn;
            float hn = og * tanhf(cn);
            int lane_p = (b & 7) * 4 + e;
            int ai     = ((b >> 3) & 1) | (qlo << 1);
            hdst[((mt * 64 + kt_o) * 32 + lane_p) * 4 + ai] = f2tf32(hn);
            // fp16 for downstream fp16 GEMMs (same 10-bit mantissa as tf32)
            hseq[(size_t)(b * T_ + t) * H_ + j0 + jj] = __float2half_rn(hn);
        }

        if (t < T_ - 1) {
            __syncthreads();
            if (tid == 0) {
                unsigned old = atom_add_rel(&g_cnt);
                if (old == (unsigned)(NB_ * (t + 1) - 1))
                    st_rel(&g_sense, (unsigned)(t + 1));
            }
        }
    }
}

// ---------------------------------------------------------------------------
extern "C" void kernel_launch(void* const* d_in, const int* in_sizes, int n_in,
                              void* d_out, int out_size) {
    (void)in_sizes; (void)n_in; (void)out_size;
    const int*   sentence = (const int*)d_in[0];
    const float* features = (const float*)d_in[1];
    const float* emb   = (const float*)d_in[3];
    const float* W_ih0 = (const float*)d_in[4];
    const float* W_hh0 = (const float*)d_in[5];
    const float* b_ih0 = (const float*)d_in[6];
    const float* b_hh0 = (const float*)d_in[7];
    const float* W_ih1 = (const float*)d_in[8];
    const float* W_hh1 = (const float*)d_in[9];
    const float* b_ih1 = (const float*)d_in[10];
    const float* b_hh1 = (const float*)d_in[11];
    const float* fc_W  = (const float*)d_in[12];
    const float* fc_b  = (const float*)d_in[13];
    float* out = (float*)d_out;

    float *xp;
    __half *x0, *hseq, *wih0, *wih1, *fcw;
    uint32_t *hf0, *hf1;
    cudaGetSymbolAddress((void**)&x0, g_x0);
    cudaGetSymbolAddress((void**)&xp, g_xp);
    cudaGetSymbolAddress((void**)&hseq, g_hseq);
    cudaGetSymbolAddress((void**)&hf0, g_hf0);
    cudaGetSymbolAddress((void**)&hf1, g_hf1);
    cudaGetSymbolAddress((void**)&wih0, g_wih0);
    cudaGetSymbolAddress((void**)&wih1, g_wih1);
    cudaGetSymbolAddress((void**)&fcw, g_fcw);

    cudaFuncSetAttribute(lstm_layer,
                         cudaFuncAttributeMaxDynamicSharedMemorySize, 196608);
    cudaFuncSetAttribute(gemm2h<0>,
                         cudaFuncAttributeMaxDynamicSharedMemorySize, 4 * HSTG);
    cudaFuncSetAttribute(gemm2h<1>,
                         cudaFuncAttributeMaxDynamicSharedMemorySize, 4 * HSTG);

    // weights -> fp16 (once per replay)
    to_half<<<(G4_ * E_ / 4 + 255) / 256, 256>>>(W_ih0, wih0, G4_ * E_ / 4);
    to_half<<<(G4_ * H_ / 4 + 255) / 256, 256>>>(W_ih1, wih1, G4_ * H_ / 4);
    to_half<<<(V_ * H_ / 4 + 255) / 256, 256>>>(fc_W, fcw, V_ * H_ / 4);

    build_x0<<<(M_ * (E_ / 4) + 255) / 256, 256>>>(sentence, features, emb, x0);

    gemm2h<0><<<dim3(G4_ / 256, M_ / 128), 256, 4 * HSTG>>>(
        x0, wih0, b_ih0, b_hh0, xp, M_, G4_, E_);
    reset_bar<<<1, 1>>>();
    lstm_layer<<<NB_, 256, 196608>>>(xp, W_hh0, hf0, hf1, hseq);

    gemm2h<0><<<dim3(G4_ / 256, M_ / 128), 256, 4 * HSTG>>>(
        hseq, wih1, b_ih1, b_hh1, xp, M_, G4_, H_);
    reset_bar<<<1, 1>>>();
    lstm_layer<<<NB_, 256, 196608>>>(xp, W_hh1, hf0, hf1, hseq);

    gemm2h<1><<<dim3(V_ / 256, M_ / 128), 256, 4 * HSTG>>>(
        hseq, fcw, fc_b, nullptr, out, M_, V_, H_);
}

// round 8
// speedup vs baseline: 1.6942x; 1.3733x over previous
#include <cuda_runtime.h>
#include <cuda_fp16.h>
#include <cstdint>

// ---------------------------------------------------------------------------
// Decoder: emb gather + concat -> wavefront-fused LSTM x2 -> FC
// B=64, T=32, E=H=512, V=32000.
// LSTM: fp16 HMMA m16n8k16, both layers concurrent (1-step skew), layer-2
// input projection fused into its mma (K=1024). FC/proj: fp16 cp.async GEMM.
// ---------------------------------------------------------------------------
#define B_  64
#define T_  32
#define E_  512
#define H_  512
#define V_  32000
#define M_  (B_ * T_)    // 2048
#define G4_ (4 * H_)     // 2048

__device__ __half   g_x0[M_ * E_];
__device__ float    g_xp[M_ * G4_];
__device__ __half   g_hseq[M_ * H_];
__device__ __half   g_wih0[G4_ * E_];
__device__ __half   g_wih1[G4_ * H_];
__device__ __half   g_fcw[V_ * H_];
__device__ __align__(16) __half g_h1ring[4][B_ * H_];  // frag-layout h1 ring
__device__ __align__(16) __half g_h2f[2][B_ * H_];     // frag-layout h2
__device__ unsigned g_cnt1, g_sense1, g_cnt2, g_sense2;

// ---------------------------------------------------------------------------
__device__ __forceinline__ uint32_t packh2(float a, float b) {
    __half2 h = __floats2half2_rn(a, b);
    return *(uint32_t*)&h;
}

__device__ __forceinline__ void mma_f16(float (&c)[4], const uint32_t (&a)[4],
                                        const uint32_t (&b)[2]) {
    asm volatile(
        "mma.sync.aligned.m16n8k16.row.col.f32.f16.f16.f32 "
        "{%0,%1,%2,%3}, {%4,%5,%6,%7}, {%8,%9}, {%0,%1,%2,%3};\n"
        : "+f"(c[0]), "+f"(c[1]), "+f"(c[2]), "+f"(c[3])
        : "r"(a[0]), "r"(a[1]), "r"(a[2]), "r"(a[3]), "r"(b[0]), "r"(b[1]));
}

__device__ __forceinline__ unsigned atom_add_rel(unsigned* p) {
    unsigned old;
    asm volatile("atom.release.gpu.global.add.u32 %0, [%1], 1;"
                 : "=r"(old) : "l"(p) : "memory");
    return old;
}
__device__ __forceinline__ void st_rel(unsigned* p, unsigned v) {
    asm volatile("st.release.gpu.global.u32 [%0], %1;" :: "l"(p), "r"(v)
                 : "memory");
}
__device__ __forceinline__ unsigned ld_acq(unsigned* p) {
    unsigned v;
    asm volatile("ld.acquire.gpu.global.u32 %0, [%1];" : "=r"(v) : "l"(p)
                 : "memory");
    return v;
}

__device__ __forceinline__ uint32_t smem_u32(const void* p) {
    uint32_t a;
    asm("{ .reg .u64 t; cvta.to.shared.u64 t, %1; cvt.u32.u64 %0, t; }"
        : "=r"(a) : "l"(p));
    return a;
}

__device__ __forceinline__ void cp16(uint32_t dst, const void* src) {
    asm volatile("cp.async.cg.shared.global [%0], [%1], 16;\n"
                 :: "r"(dst), "l"(src));
}

// Store one fp16 h value into the m16n8k16 A-fragment layout.
// Layout: uint4 per (mt, kt16, lane): {a0,a1,a2,a3}; a_q holds rows
// g+8*(q&1), halves k0+8*(q>>1)+{0,1} with g=lane>>2, k0=(lane&3)*2.
__device__ __forceinline__ void st_hfrag(__half* base, int b, int j, __half h) {
    int mt     = b >> 4;
    int kt     = j >> 4;
    int lane_t = (b & 7) * 4 + ((j >> 1) & 3);
    int q      = ((b >> 3) & 1) | (((j >> 3) & 1) << 1);
    base[(((mt * 32 + kt) * 32 + lane_t) << 3) + (q << 1) + (j & 1)] = h;
}

// ---------------------------------------------------------------------------
__global__ void to_half(const float* __restrict__ src, __half* __restrict__ dst,
                        int n4) {
    int i = blockIdx.x * blockDim.x + threadIdx.x;
    if (i >= n4) return;
    float4 v = *(const float4*)(src + (size_t)i * 4);
    uint2 u;
    u.x = packh2(v.x, v.y);
    u.y = packh2(v.z, v.w);
    *(uint2*)(dst + (size_t)i * 4) = u;
}

__global__ void build_x0(const int* __restrict__ sentence,
                         const float* __restrict__ features,
                         const float* __restrict__ emb,
                         __half* __restrict__ x0) {
    int i4 = blockIdx.x * blockDim.x + threadIdx.x;
    if (i4 >= M_ * (E_ / 4)) return;
    int m  = i4 >> 7;
    int e4 = (i4 & 127) * 4;
    int b  = m >> 5;
    int t  = m & 31;
    float4 v;
    if (t == 0) {
        v = *(const float4*)&features[b * E_ + e4];
    } else {
        int tok = sentence[b * T_ + (t - 1)];
        v = *(const float4*)&emb[tok * E_ + e4];
    }
    uint2 u;
    u.x = packh2(v.x, v.y);
    u.y = packh2(v.z, v.w);
    *(uint2*)(x0 + (size_t)m * E_ + e4) = u;
}

__global__ void reset_bar() { g_cnt1 = 0; g_sense1 = 0; g_cnt2 = 0; g_sense2 = 0; }

// ---------------------------------------------------------------------------
// fp16 GEMM (round-7, proven): cp.async 4-stage, BM=128 BN=256, m16n8k16.
// ---------------------------------------------------------------------------
#define HLDW 20
#define HSTG ((128 + 256) * HLDW * 4)

template <int MODE>
__global__ void __launch_bounds__(256)
gemm2h(const __half* __restrict__ A, const __half* __restrict__ Bm,
       const float* __restrict__ bias1, const float* __restrict__ bias2,
       float* __restrict__ C, int M, int N, int K) {
    extern __shared__ uint8_t dsm[];
    const uint32_t base = smem_u32(dsm);

    const int tid  = threadIdx.x;
    const int lane = tid & 31;
    const int warp = tid >> 5;
    const int wm = (warp & 1) * 64;
    const int wn = (warp >> 1) * 64;
    const int m0 = blockIdx.y * 128;
    const int n0 = blockIdx.x * 256;

    float acc[4][8][4];
#pragma unroll
    for (int mt = 0; mt < 4; mt++)
#pragma unroll
        for (int nt = 0; nt < 8; nt++)
#pragma unroll
            for (int i = 0; i < 4; i++) acc[mt][nt][i] = 0.f;

    auto issue = [&](int s) {
        uint32_t sa = base + (s & 3) * HSTG;
        uint32_t sb = sa + 128 * HLDW * 4;
        const __half* ap = A + (size_t)m0 * K + s * 32;
        const __half* wp = Bm + (size_t)n0 * K + s * 32;
#pragma unroll
        for (int i = 0; i < 2; i++) {
            int c = i * 256 + tid;
            int row = c >> 2, kk = c & 3;
            cp16(sa + (uint32_t)(row * 80 + kk * 16),
                 ap + (size_t)row * K + kk * 8);
        }
#pragma unroll
        for (int i = 0; i < 4; i++) {
            int c = i * 256 + tid;
            int row = c >> 2, kk = c & 3;
            cp16(sb + (uint32_t)(row * 80 + kk * 16),
                 wp + (size_t)row * K + kk * 8);
        }
    };

#pragma unroll
    for (int s = 0; s < 3; s++) {
        issue(s);
        asm volatile("cp.async.commit_group;" ::: "memory");
    }

    for (int k = 0; k < 16; k++) {
        if (k <= 13)      asm volatile("cp.async.wait_group 2;" ::: "memory");
        else if (k == 14) asm volatile("cp.async.wait_group 1;" ::: "memory");
        else              asm volatile("cp.async.wait_group 0;" ::: "memory");
        __syncthreads();
        if (k + 3 < 16) {
            issue(k + 3);
            asm volatile("cp.async.commit_group;" ::: "memory");
        }

        const uint32_t* As = (const uint32_t*)(dsm + (size_t)(k & 3) * HSTG);
        const uint32_t* Bs = As + 128 * HLDW;
#pragma unroll
        for (int ks = 0; ks < 2; ks++) {
            int kc = ks * 8 + (lane & 3);
            uint32_t bf[8][2];
#pragma unroll
            for (int nt = 0; nt < 8; nt++) {
                int nr = wn + nt * 8 + (lane >> 2);
                bf[nt][0] = Bs[nr * HLDW + kc];
                bf[nt][1] = Bs[nr * HLDW + kc + 4];
            }
#pragma unroll
            for (int mt = 0; mt < 4; mt++) {
                int r = wm + mt * 16 + (lane >> 2);
                uint32_t af[4];
                af[0] = As[r * HLDW + kc];
                af[1] = As[(r + 8) * HLDW + kc];
                af[2] = As[r * HLDW + kc + 4];
                af[3] = As[(r + 8) * HLDW + kc + 4];
#pragma unroll
                for (int nt = 0; nt < 8; nt++)
                    mma_f16(acc[mt][nt], af, bf[nt]);
            }
        }
    }

#pragma unroll
    for (int nt = 0; nt < 8; nt++) {
        int cn  = n0 + wn + nt * 8 + (lane & 3) * 2;
        float bv0 = bias1[cn];
        float bv1 = bias1[cn + 1];
        if (MODE == 0 && bias2) { bv0 += bias2[cn]; bv1 += bias2[cn + 1]; }
#pragma unroll
        for (int mt = 0; mt < 4; mt++) {
            int r = m0 + wm + mt * 16 + (lane >> 2);
            float v0 = acc[mt][nt][0] + bv0;
            float v1 = acc[mt][nt][1] + bv1;
            float v2 = acc[mt][nt][2] + bv0;
            float v3 = acc[mt][nt][3] + bv1;
            if (MODE == 0) {
                C[(size_t)r * N + cn]           = v0;
                C[(size_t)r * N + cn + 1]       = v1;
                C[(size_t)(r + 8) * N + cn]     = v2;
                C[(size_t)(r + 8) * N + cn + 1] = v3;
            } else {
                int b1 = r >> 5, t1 = r & 31;
                int b2 = (r + 8) >> 5, t2 = (r + 8) & 31;
                size_t base1 = (size_t)b1 * N * T_ + t1;
                size_t base2 = (size_t)b2 * N * T_ + t2;
                C[base1 + (size_t)cn * T_]       = v0;
                C[base1 + (size_t)(cn + 1) * T_] = v1;
                C[base2 + (size_t)cn * T_]       = v2;
                C[base2 + (size_t)(cn + 1) * T_] = v3;
            }
        }
    }
}

// ---------------------------------------------------------------------------
// Wavefront LSTM: 128 blocks. Blocks 0-63 = layer 1 (K=512, W_hh0);
// blocks 64-127 = layer 2 fused (K=1024: warps 0-3 h1*W_ih1, warps 4-7
// h2*W_hh1). Layer 2 trails layer 1 by one step. fp16 mma, fp32 reduce.
// ---------------------------------------------------------------------------
__global__ void __launch_bounds__(256, 1)
lstm_wave(const float* __restrict__ xp0, const float* __restrict__ Whh0,
          const __half* __restrict__ wih1, const float* __restrict__ Whh1,
          const float* __restrict__ bih1, const float* __restrict__ bhh1,
          __half* __restrict__ hseq) {
    extern __shared__ uint32_t smu[];
    const int tid  = threadIdx.x;
    const int lane = tid & 31;
    const int w    = tid >> 5;
    const int gid  = lane >> 2;
    const int tig  = lane & 3;
    const int jj   = tid & 7;
    const int bq   = tid >> 3;
    float creg0 = 0.f, creg1 = 0.f;

    if (blockIdx.x < 64) {
        // ================= layer 1 =================
        uint32_t* hsf = smu;                    // 64KB: [mt4][kt32][lane32][4]
        float*    red = (float*)(smu + 16384);  // 64KB
        const int j0 = blockIdx.x * 8;

        uint32_t bfr[4][4][2];
#pragma unroll
        for (int nt = 0; nt < 4; nt++)
#pragma unroll
            for (int ktl = 0; ktl < 4; ktl++) {
                int n  = nt * H_ + j0 + gid;
                int kb = w * 64 + ktl * 16 + tig * 2;
                const float* wr = Whh0 + (size_t)n * H_;
                bfr[nt][ktl][0] = packh2(wr[kb],     wr[kb + 1]);
                bfr[nt][ktl][1] = packh2(wr[kb + 8], wr[kb + 9]);
            }

#pragma unroll 4
        for (int i = tid; i < 4096; i += 256)
            ((uint4*)hsf)[i] = make_uint4(0u, 0u, 0u, 0u);

        for (int t = 0; t < T_; t++) {
            float xpr[2][4];
#pragma unroll
            for (int half = 0; half < 2; half++) {
                int b = bq + half * 32;
#pragma unroll
                for (int g = 0; g < 4; g++)
                    xpr[half][g] =
                        xp0[(size_t)(b * T_ + t) * G4_ + g * H_ + j0 + jj];
            }

            if (t > 0) {
                if (tid == 0) {
                    while (ld_acq(&g_sense1) < (unsigned)t) { }
                    if (t >= 4)
                        while (ld_acq(&g_sense2) < (unsigned)(t - 3)) { }
                }
                __syncthreads();
                const uint4* src = (const uint4*)g_h1ring[(t - 1) & 3];
#pragma unroll
                for (int it = 0; it < 16; it++) {
                    int idx = it * 256 + tid;
                    ((uint4*)hsf)[idx] = __ldcg(src + idx);
                }
            }
            __syncthreads();

            float acc[4][4][4];
#pragma unroll
            for (int mt = 0; mt < 4; mt++)
#pragma unroll
                for (int nt = 0; nt < 4; nt++)
#pragma unroll
                    for (int i = 0; i < 4; i++) acc[mt][nt][i] = 0.f;

#pragma unroll
            for (int ktl = 0; ktl < 4; ktl++) {
                int kt = w * 4 + ktl;
#pragma unroll
                for (int mt = 0; mt < 4; mt++) {
                    uint4 av = *(const uint4*)&hsf[(((mt * 32 + kt) * 32) + lane) * 4];
                    uint32_t a[4] = {av.x, av.y, av.z, av.w};
#pragma unroll
                    for (int nt = 0; nt < 4; nt++)
                        mma_f16(acc[mt][nt], a, bfr[nt][ktl]);
                }
            }

#pragma unroll
            for (int mt = 0; mt < 4; mt++)
#pragma unroll
                for (int nt = 0; nt < 4; nt++)
                    *(float4*)&red[(((w * 4 + mt) * 4 + nt) << 7) + lane * 4] =
                        make_float4(acc[mt][nt][0], acc[mt][nt][1],
                                    acc[mt][nt][2], acc[mt][nt][3]);
            __syncthreads();

            __half* ring = g_h1ring[t & 3];
#pragma unroll
            for (int half = 0; half < 2; half++) {
                int b     = bq + half * 32;
                int row_t = b & 15;
                int mt    = b >> 4;
                int pos   = (((row_t & 7) * 4 + (jj >> 1)) << 2) + (jj & 1) +
                            ((row_t >> 3) << 1);
                float gv[4];
#pragma unroll
                for (int g = 0; g < 4; g++) {
                    float s = xpr[half][g];
#pragma unroll
                    for (int ww = 0; ww < 8; ww++)
                        s += red[(((ww * 4 + mt) * 4 + g) << 7) + pos];
                    gv[g] = s;
                }
                float ig = 1.f / (1.f + __expf(-gv[0]));
                float fg = 1.f / (1.f + __expf(-gv[1]));
                float gg = tanhf(gv[2]);
                float og = 1.f / (1.f + __expf(-gv[3]));
                float cold = half ? creg1 : creg0;
                float cn = fg * cold + ig * gg;
                if (half) creg1 = cn; else creg0 = cn;
                float hn = og * tanhf(cn);
                st_hfrag(ring, b, j0 + jj, __float2half_rn(hn));
            }

            __syncthreads();
            if (tid == 0) {
                unsigned old = atom_add_rel(&g_cnt1);
                if (old == 64u * (t + 1) - 1) st_rel(&g_sense1, (unsigned)(t + 1));
            }
        }
    } else {
        // ================= layer 2 (fused input projection) =================
        uint32_t* hsfA = smu;                    // 64KB h1
        uint32_t* hsfB = smu + 16384;            // 64KB h2
        float*    red  = (float*)(smu + 32768);  // 64KB
        const int j0 = (blockIdx.x - 64) * 8;
        const int wq = w & 3;
        const bool isH1 = (w < 4);

        uint32_t bfr[4][8][2];
#pragma unroll
        for (int nt = 0; nt < 4; nt++)
#pragma unroll
            for (int ktl = 0; ktl < 8; ktl++) {
                int n  = nt * H_ + j0 + gid;
                int kb = wq * 128 + ktl * 16 + tig * 2;
                if (isH1) {
                    bfr[nt][ktl][0] = *(const uint32_t*)&wih1[(size_t)n * H_ + kb];
                    bfr[nt][ktl][1] = *(const uint32_t*)&wih1[(size_t)n * H_ + kb + 8];
                } else {
                    const float* wr = Whh1 + (size_t)n * H_;
                    bfr[nt][ktl][0] = packh2(wr[kb],     wr[kb + 1]);
                    bfr[nt][ktl][1] = packh2(wr[kb + 8], wr[kb + 9]);
                }
            }

        float bs[4];
#pragma unroll
        for (int g = 0; g < 4; g++)
            bs[g] = bih1[g * H_ + j0 + jj] + bhh1[g * H_ + j0 + jj];

#pragma unroll 4
        for (int i = tid; i < 4096; i += 256)
            ((uint4*)hsfB)[i] = make_uint4(0u, 0u, 0u, 0u);

        for (int s = 0; s < T_; s++) {
            if (tid == 0) {
                while (ld_acq(&g_sense1) < (unsigned)(s + 1)) { }
                if (s > 0)
                    while (ld_acq(&g_sense2) < (unsigned)s) { }
            }
            __syncthreads();
            {
                const uint4* srcA = (const uint4*)g_h1ring[s & 3];
#pragma unroll
                for (int it = 0; it < 16; it++) {
                    int idx = it * 256 + tid;
                    ((uint4*)hsfA)[idx] = __ldcg(srcA + idx);
                }
                if (s > 0) {
                    const uint4* srcB = (const uint4*)g_h2f[(s - 1) & 1];
#pragma unroll
                    for (int it = 0; it < 16; it++) {
                        int idx = it * 256 + tid;
                        ((uint4*)hsfB)[idx] = __ldcg(srcB + idx);
                    }
                }
            }
            __syncthreads();

            float acc[4][4][4];
#pragma unroll
            for (int mt = 0; mt < 4; mt++)
#pragma unroll
                for (int nt = 0; nt < 4; nt++)
#pragma unroll
                    for (int i = 0; i < 4; i++) acc[mt][nt][i] = 0.f;

            const uint32_t* src = isH1 ? hsfA : hsfB;
#pragma unroll
            for (int ktl = 0; ktl < 8; ktl++) {
                int kt = wq * 8 + ktl;
#pragma unroll
                for (int mt = 0; mt < 4; mt++) {
                    uint4 av = *(const uint4*)&src[(((mt * 32 + kt) * 32) + lane) * 4];
                    uint32_t a[4] = {av.x, av.y, av.z, av.w};
#pragma unroll
                    for (int nt = 0; nt < 4; nt++)
                        mma_f16(acc[mt][nt], a, bfr[nt][ktl]);
                }
            }

#pragma unroll
            for (int mt = 0; mt < 4; mt++)
#pragma unroll
                for (int nt = 0; nt < 4; nt++)
                    *(float4*)&red[(((w * 4 + mt) * 4 + nt) << 7) + lane * 4] =
                        make_float4(acc[mt][nt][0], acc[mt][nt][1],
                                    acc[mt][nt][2], acc[mt][nt][3]);
            __syncthreads();

            __half* ring = g_h2f[s & 1];
#pragma unroll
            for (int half = 0; half < 2; half++) {
                int b     = bq + half * 32;
                int row_t = b & 15;
                int mt    = b >> 4;
                int pos   = (((row_t & 7) * 4 + (jj >> 1)) << 2) + (jj & 1) +
                            ((row_t >> 3) << 1);
                float gv[4];
#pragma unroll
                for (int g = 0; g < 4; g++) {
                    float sacc = bs[g];
#pragma unroll
                    for (int ww = 0; ww < 8; ww++)
                        sacc += red[(((ww * 4 + mt) * 4 + g) << 7) + pos];
                    gv[g] = sacc;
                }
                float ig = 1.f / (1.f + __expf(-gv[0]));
                float fg = 1.f / (1.f + __expf(-gv[1]));
                float gg = tanhf(gv[2]);
                float og = 1.f / (1.f + __expf(-gv[3]));
                float cold = half ? creg1 : creg0;
                float cn = fg * cold + ig * gg;
                if (half) creg1 = cn; else creg0 = cn;
                float hn = og * tanhf(cn);
                __half hb = __float2half_rn(hn);
                st_hfrag(ring, b, j0 + jj, hb);
                hseq[(size_t)(b * T_ + s) * H_ + j0 + jj] = hb;
            }

            __syncthreads();
            if (tid == 0) {
                unsigned old = atom_add_rel(&g_cnt2);
                if (old == 64u * (s + 1) - 1) st_rel(&g_sense2, (unsigned)(s + 1));
            }
        }
    }
}

// ---------------------------------------------------------------------------
extern "C" void kernel_launch(void* const* d_in, const int* in_sizes, int n_in,
                              void* d_out, int out_size) {
    (void)in_sizes; (void)n_in; (void)out_size;
    const int*   sentence = (const int*)d_in[0];
    const float* features = (const float*)d_in[1];
    const float* emb   = (const float*)d_in[3];
    const float* W_ih0 = (const float*)d_in[4];
    const float* W_hh0 = (const float*)d_in[5];
    const float* b_ih0 = (const float*)d_in[6];
    const float* b_hh0 = (const float*)d_in[7];
    const float* W_ih1 = (const float*)d_in[8];
    const float* W_hh1 = (const float*)d_in[9];
    const float* b_ih1 = (const float*)d_in[10];
    const float* b_hh1 = (const float*)d_in[11];
    const float* fc_W  = (const float*)d_in[12];
    const float* fc_b  = (const float*)d_in[13];
    float* out = (float*)d_out;

    float *xp;
    __half *x0, *hseq, *wih0, *wih1, *fcw;
    cudaGetSymbolAddress((void**)&x0, g_x0);
    cudaGetSymbolAddress((void**)&xp, g_xp);
    cudaGetSymbolAddress((void**)&hseq, g_hseq);
    cudaGetSymbolAddress((void**)&wih0, g_wih0);
    cudaGetSymbolAddress((void**)&wih1, g_wih1);
    cudaGetSymbolAddress((void**)&fcw, g_fcw);

    cudaFuncSetAttribute(lstm_wave,
                         cudaFuncAttributeMaxDynamicSharedMemorySize, 196608);
    cudaFuncSetAttribute(gemm2h<0>,
                         cudaFuncAttributeMaxDynamicSharedMemorySize, 4 * HSTG);
    cudaFuncSetAttribute(gemm2h<1>,
                         cudaFuncAttributeMaxDynamicSharedMemorySize, 4 * HSTG);

    to_half<<<(G4_ * E_ / 4 + 255) / 256, 256>>>(W_ih0, wih0, G4_ * E_ / 4);
    to_half<<<(G4_ * H_ / 4 + 255) / 256, 256>>>(W_ih1, wih1, G4_ * H_ / 4);
    to_half<<<(V_ * H_ / 4 + 255) / 256, 256>>>(fc_W, fcw, V_ * H_ / 4);

    build_x0<<<(M_ * (E_ / 4) + 255) / 256, 256>>>(sentence, features, emb, x0);

    // layer-0 input projection (bias folded)
    gemm2h<0><<<dim3(G4_ / 256, M_ / 128), 256, 4 * HSTG>>>(
        x0, wih0, b_ih0, b_hh0, xp, M_, G4_, E_);

    reset_bar<<<1, 1>>>();
    lstm_wave<<<128, 256, 196608>>>(xp, W_hh0, wih1, W_hh1, b_ih1, b_hh1, hseq);

    gemm2h<1><<<dim3(V_ / 256, M_ / 128), 256, 4 * HSTG>>>(
        hseq, fcw, fc_b, nullptr, out, M_, V_, H_);
}

// round 9
// speedup vs baseline: 1.7771x; 1.0489x over previous
#include <cuda_runtime.h>
#include <cuda_fp16.h>
#include <cstdint>

// ---------------------------------------------------------------------------
// Decoder: emb gather + concat -> wavefront-fused LSTM x2 -> FC
// B=64, T=32, E=H=512, V=32000.
// GEMMs: fp16 HMMA m16n8k16, BM=128 BN=128, 2 CTAs/SM (4 warps/SMSP).
// LSTM: wavefront (both layers concurrent), flag-array barriers.
// ---------------------------------------------------------------------------
#define B_  64
#define T_  32
#define E_  512
#define H_  512
#define V_  32000
#define M_  (B_ * T_)    // 2048
#define G4_ (4 * H_)     // 2048

__device__ __half   g_x0[M_ * E_];
__device__ float    g_xp[M_ * G4_];
__device__ __half   g_hseq[M_ * H_];
__device__ __half   g_wih0[G4_ * E_];
__device__ __half   g_wih1[G4_ * H_];
__device__ __half   g_fcw[V_ * H_];
__device__ __align__(16) __half g_h1ring[4][B_ * H_];  // frag-layout h1 ring
__device__ __align__(16) __half g_h2f[2][B_ * H_];     // frag-layout h2
__device__ unsigned g_flags1[64 * 4];   // per-block step counters, stride 16B
__device__ unsigned g_flags2[64 * 4];

// ---------------------------------------------------------------------------
__device__ __forceinline__ uint32_t packh2(float a, float b) {
    __half2 h = __floats2half2_rn(a, b);
    return *(uint32_t*)&h;
}

__device__ __forceinline__ void mma_f16(float (&c)[4], const uint32_t (&a)[4],
                                        const uint32_t (&b)[2]) {
    asm volatile(
        "mma.sync.aligned.m16n8k16.row.col.f32.f16.f16.f32 "
        "{%0,%1,%2,%3}, {%4,%5,%6,%7}, {%8,%9}, {%0,%1,%2,%3};\n"
        : "+f"(c[0]), "+f"(c[1]), "+f"(c[2]), "+f"(c[3])
        : "r"(a[0]), "r"(a[1]), "r"(a[2]), "r"(a[3]), "r"(b[0]), "r"(b[1]));
}

__device__ __forceinline__ void st_rel(unsigned* p, unsigned v) {
    asm volatile("st.release.gpu.global.u32 [%0], %1;" :: "l"(p), "r"(v)
                 : "memory");
}
__device__ __forceinline__ unsigned ld_acq(unsigned* p) {
    unsigned v;
    asm volatile("ld.acquire.gpu.global.u32 %0, [%1];" : "=r"(v) : "l"(p)
                 : "memory");
    return v;
}

__device__ __forceinline__ uint32_t smem_u32(const void* p) {
    uint32_t a;
    asm("{ .reg .u64 t; cvta.to.shared.u64 t, %1; cvt.u32.u64 %0, t; }"
        : "=r"(a) : "l"(p));
    return a;
}

__device__ __forceinline__ void cp16(uint32_t dst, const void* src) {
    asm volatile("cp.async.cg.shared.global [%0], [%1], 16;\n"
                 :: "r"(dst), "l"(src));
}

// m16n8k16 A-fragment-layout store (h ring buffers)
__device__ __forceinline__ void st_hfrag(__half* base, int b, int j, __half h) {
    int mt     = b >> 4;
    int kt     = j >> 4;
    int lane_t = (b & 7) * 4 + ((j >> 1) & 3);
    int q      = ((b >> 3) & 1) | (((j >> 3) & 1) << 1);
    base[(((mt * 32 + kt) * 32 + lane_t) << 3) + (q << 1) + (j & 1)] = h;
}

// ---------------------------------------------------------------------------
__global__ void to_half(const float* __restrict__ src, __half* __restrict__ dst,
                        int n4) {
    int i = blockIdx.x * blockDim.x + threadIdx.x;
    if (i >= n4) return;
    float4 v = *(const float4*)(src + (size_t)i * 4);
    uint2 u;
    u.x = packh2(v.x, v.y);
    u.y = packh2(v.z, v.w);
    *(uint2*)(dst + (size_t)i * 4) = u;
}

__global__ void build_x0(const int* __restrict__ sentence,
                         const float* __restrict__ features,
                         const float* __restrict__ emb,
                         __half* __restrict__ x0) {
    int i4 = blockIdx.x * blockDim.x + threadIdx.x;
    if (i4 >= M_ * (E_ / 4)) return;
    int m  = i4 >> 7;
    int e4 = (i4 & 127) * 4;
    int b  = m >> 5;
    int t  = m & 31;
    float4 v;
    if (t == 0) {
        v = *(const float4*)&features[b * E_ + e4];
    } else {
        int tok = sentence[b * T_ + (t - 1)];
        v = *(const float4*)&emb[tok * E_ + e4];
    }
    uint2 u;
    u.x = packh2(v.x, v.y);
    u.y = packh2(v.z, v.w);
    *(uint2*)(x0 + (size_t)m * E_ + e4) = u;
}

__global__ void reset_bar() {
    int i = threadIdx.x;
    if (i < 256) { g_flags1[i] = 0; g_flags2[i] = 0; }
}

// ---------------------------------------------------------------------------
// fp16 GEMM: cp.async 4-stage, BM=128 BN=128 BK=32, 256 thr, 2 CTAs/SM.
// Warp tile 64x32 (8 warps: 2m x 4n), m16n8k16, fp32 accumulate.
// K = 512. MODE 0: row-major C + bias1(+bias2). MODE 1: out[b,n,t].
// smem/stage = (128+128)*80 = 20480B; 4 stages = 81920B (x2 CTA = 160KB/SM).
// ---------------------------------------------------------------------------
#define HLDW 20
#define HSTG ((128 + 128) * HLDW * 4)

template <int MODE>
__global__ void __launch_bounds__(256, 2)
gemm2h(const __half* __restrict__ A, const __half* __restrict__ Bm,
       const float* __restrict__ bias1, const float* __restrict__ bias2,
       float* __restrict__ C, int M, int N, int K) {
    extern __shared__ uint8_t dsm[];
    const uint32_t base = smem_u32(dsm);

    const int tid  = threadIdx.x;
    const int lane = tid & 31;
    const int warp = tid >> 5;
    const int wm = (warp & 1) * 64;
    const int wn = (warp >> 1) * 32;
    const int m0 = blockIdx.y * 128;
    const int n0 = blockIdx.x * 128;

    float acc[4][4][4];
#pragma unroll
    for (int mt = 0; mt < 4; mt++)
#pragma unroll
        for (int nt = 0; nt < 4; nt++)
#pragma unroll
            for (int i = 0; i < 4; i++) acc[mt][nt][i] = 0.f;

    auto issue = [&](int s) {
        uint32_t sa = base + (s & 3) * HSTG;
        uint32_t sb = sa + 128 * HLDW * 4;
        const __half* ap = A + (size_t)m0 * K + s * 32;
        const __half* wp = Bm + (size_t)n0 * K + s * 32;
#pragma unroll
        for (int i = 0; i < 2; i++) {
            int c = i * 256 + tid;
            int row = c >> 2, kk = c & 3;
            cp16(sa + (uint32_t)(row * 80 + kk * 16),
                 ap + (size_t)row * K + kk * 8);
        }
#pragma unroll
        for (int i = 0; i < 2; i++) {
            int c = i * 256 + tid;
            int row = c >> 2, kk = c & 3;
            cp16(sb + (uint32_t)(row * 80 + kk * 16),
                 wp + (size_t)row * K + kk * 8);
        }
    };

#pragma unroll
    for (int s = 0; s < 3; s++) {
        issue(s);
        asm volatile("cp.async.commit_group;" ::: "memory");
    }

    for (int k = 0; k < 16; k++) {
        if (k <= 13)      asm volatile("cp.async.wait_group 2;" ::: "memory");
        else if (k == 14) asm volatile("cp.async.wait_group 1;" ::: "memory");
        else              asm volatile("cp.async.wait_group 0;" ::: "memory");
        __syncthreads();
        if (k + 3 < 16) {
            issue(k + 3);
            asm volatile("cp.async.commit_group;" ::: "memory");
        }

        const uint32_t* As = (const uint32_t*)(dsm + (size_t)(k & 3) * HSTG);
        const uint32_t* Bs = As + 128 * HLDW;
#pragma unroll
        for (int ks = 0; ks < 2; ks++) {
            int kc = ks * 8 + (lane & 3);
            uint32_t bf[4][2];
#pragma unroll
            for (int nt = 0; nt < 4; nt++) {
                int nr = wn + nt * 8 + (lane >> 2);
                bf[nt][0] = Bs[nr * HLDW + kc];
                bf[nt][1] = Bs[nr * HLDW + kc + 4];
            }
#pragma unroll
            for (int mt = 0; mt < 4; mt++) {
                int r = wm + mt * 16 + (lane >> 2);
                uint32_t af[4];
                af[0] = As[r * HLDW + kc];
                af[1] = As[(r + 8) * HLDW + kc];
                af[2] = As[r * HLDW + kc + 4];
                af[3] = As[(r + 8) * HLDW + kc + 4];
#pragma unroll
                for (int nt = 0; nt < 4; nt++)
                    mma_f16(acc[mt][nt], af, bf[nt]);
            }
        }
    }

#pragma unroll
    for (int nt = 0; nt < 4; nt++) {
        int cn  = n0 + wn + nt * 8 + (lane & 3) * 2;
        float bv0 = bias1[cn];
        float bv1 = bias1[cn + 1];
        if (MODE == 0 && bias2) { bv0 += bias2[cn]; bv1 += bias2[cn + 1]; }
#pragma unroll
        for (int mt = 0; mt < 4; mt++) {
            int r = m0 + wm + mt * 16 + (lane >> 2);
            float v0 = acc[mt][nt][0] + bv0;
            float v1 = acc[mt][nt][1] + bv1;
            float v2 = acc[mt][nt][2] + bv0;
            float v3 = acc[mt][nt][3] + bv1;
            if (MODE == 0) {
                C[(size_t)r * N + cn]           = v0;
                C[(size_t)r * N + cn + 1]       = v1;
                C[(size_t)(r + 8) * N + cn]     = v2;
                C[(size_t)(r + 8) * N + cn + 1] = v3;
            } else {
                int b1 = r >> 5, t1 = r & 31;
                int b2 = (r + 8) >> 5, t2 = (r + 8) & 31;
                size_t base1 = (size_t)b1 * N * T_ + t1;
                size_t base2 = (size_t)b2 * N * T_ + t2;
                C[base1 + (size_t)cn * T_]       = v0;
                C[base1 + (size_t)(cn + 1) * T_] = v1;
                C[base2 + (size_t)cn * T_]       = v2;
                C[base2 + (size_t)(cn + 1) * T_] = v3;
            }
        }
    }
}

// ---------------------------------------------------------------------------
// Wavefront LSTM: 128 blocks. 0-63 = layer 1; 64-127 = layer 2 (fused input
// projection, K=1024 split across warps). Flag-array barriers (no atomics).
// ---------------------------------------------------------------------------
__global__ void __launch_bounds__(256, 1)
lstm_wave(const float* __restrict__ xp0, const float* __restrict__ Whh0,
          const __half* __restrict__ wih1, const float* __restrict__ Whh1,
          const float* __restrict__ bih1, const float* __restrict__ bhh1,
          __half* __restrict__ hseq) {
    extern __shared__ uint32_t smu[];
    const int tid  = threadIdx.x;
    const int lane = tid & 31;
    const int w    = tid >> 5;
    const int gid  = lane >> 2;
    const int tig  = lane & 3;
    const int jj   = tid & 7;
    const int bq   = tid >> 3;
    float creg0 = 0.f, creg1 = 0.f;

    if (blockIdx.x < 64) {
        // ================= layer 1 =================
        uint32_t* hsf = smu;
        float*    red = (float*)(smu + 16384);
        const int j0 = blockIdx.x * 8;

        uint32_t bfr[4][4][2];
#pragma unroll
        for (int nt = 0; nt < 4; nt++)
#pragma unroll
            for (int ktl = 0; ktl < 4; ktl++) {
                int n  = nt * H_ + j0 + gid;
                int kb = w * 64 + ktl * 16 + tig * 2;
                const float* wr = Whh0 + (size_t)n * H_;
                bfr[nt][ktl][0] = packh2(wr[kb],     wr[kb + 1]);
                bfr[nt][ktl][1] = packh2(wr[kb + 8], wr[kb + 9]);
            }

#pragma unroll 4
        for (int i = tid; i < 4096; i += 256)
            ((uint4*)hsf)[i] = make_uint4(0u, 0u, 0u, 0u);

        for (int t = 0; t < T_; t++) {
            float xpr[2][4];
#pragma unroll
            for (int half = 0; half < 2; half++) {
                int b = bq + half * 32;
#pragma unroll
                for (int g = 0; g < 4; g++)
                    xpr[half][g] =
                        xp0[(size_t)(b * T_ + t) * G4_ + g * H_ + j0 + jj];
            }

            if (t > 0) {
                if (tid < 64) {
                    while (ld_acq(&g_flags1[tid * 4]) < (unsigned)t)
                        __nanosleep(64);
                } else if (tid < 128 && t >= 4) {
                    while (ld_acq(&g_flags2[(tid - 64) * 4]) < (unsigned)(t - 3))
                        __nanosleep(64);
                }
                __syncthreads();
                const uint4* src = (const uint4*)g_h1ring[(t - 1) & 3];
#pragma unroll
                for (int it = 0; it < 16; it++) {
                    int idx = it * 256 + tid;
                    ((uint4*)hsf)[idx] = __ldcg(src + idx);
                }
            }
            __syncthreads();

            float acc[4][4][4];
#pragma unroll
            for (int mt = 0; mt < 4; mt++)
#pragma unroll
                for (int nt = 0; nt < 4; nt++)
#pragma unroll
                    for (int i = 0; i < 4; i++) acc[mt][nt][i] = 0.f;

#pragma unroll
            for (int ktl = 0; ktl < 4; ktl++) {
                int kt = w * 4 + ktl;
#pragma unroll
                for (int mt = 0; mt < 4; mt++) {
                    uint4 av = *(const uint4*)&hsf[(((mt * 32 + kt) * 32) + lane) * 4];
                    uint32_t a[4] = {av.x, av.y, av.z, av.w};
#pragma unroll
                    for (int nt = 0; nt < 4; nt++)
                        mma_f16(acc[mt][nt], a, bfr[nt][ktl]);
                }
            }

#pragma unroll
            for (int mt = 0; mt < 4; mt++)
#pragma unroll
                for (int nt = 0; nt < 4; nt++)
                    *(float4*)&red[(((w * 4 + mt) * 4 + nt) << 7) + lane * 4] =
                        make_float4(acc[mt][nt][0], acc[mt][nt][1],
                                    acc[mt][nt][2], acc[mt][nt][3]);
            __syncthreads();

            __half* ring = g_h1ring[t & 3];
#pragma unroll
            for (int half = 0; half < 2; half++) {
                int b     = bq + half * 32;
                int row_t = b & 15;
                int mt    = b >> 4;
                int pos   = (((row_t & 7) * 4 + (jj >> 1)) << 2) + (jj & 1) +
                            ((row_t >> 3) << 1);
                float gv[4];
#pragma unroll
                for (int g = 0; g < 4; g++) {
                    float s = xpr[half][g];
#pragma unroll
                    for (int ww = 0; ww < 8; ww++)
                        s += red[(((ww * 4 + mt) * 4 + g) << 7) + pos];
                    gv[g] = s;
                }
                float ig = 1.f / (1.f + __expf(-gv[0]));
                float fg = 1.f / (1.f + __expf(-gv[1]));
                float gg = tanhf(gv[2]);
                float og = 1.f / (1.f + __expf(-gv[3]));
                float cold = half ? creg1 : creg0;
                float cn = fg * cold + ig * gg;
                if (half) creg1 = cn; else creg0 = cn;
                float hn = og * tanhf(cn);
                st_hfrag(ring, b, j0 + jj, __float2half_rn(hn));
            }

            __syncthreads();
            if (tid == 0) st_rel(&g_flags1[blockIdx.x * 4], (unsigned)(t + 1));
        }
    } else {
        // ================= layer 2 (fused input projection) =================
        uint32_t* hsfA = smu;
        uint32_t* hsfB = smu + 16384;
        float*    red  = (float*)(smu + 32768);
        const int bid2 = blockIdx.x - 64;
        const int j0 = bid2 * 8;
        const int wq = w & 3;
        const bool isH1 = (w < 4);

        uint32_t bfr[4][8][2];
#pragma unroll
        for (int nt = 0; nt < 4; nt++)
#pragma unroll
            for (int ktl = 0; ktl < 8; ktl++) {
                int n  = nt * H_ + j0 + gid;
                int kb = wq * 128 + ktl * 16 + tig * 2;
                if (isH1) {
                    bfr[nt][ktl][0] = *(const uint32_t*)&wih1[(size_t)n * H_ + kb];
                    bfr[nt][ktl][1] = *(const uint32_t*)&wih1[(size_t)n * H_ + kb + 8];
                } else {
                    const float* wr = Whh1 + (size_t)n * H_;
                    bfr[nt][ktl][0] = packh2(wr[kb],     wr[kb + 1]);
                    bfr[nt][ktl][1] = packh2(wr[kb + 8], wr[kb + 9]);
                }
            }

        float bs[4];
#pragma unroll
        for (int g = 0; g < 4; g++)
            bs[g] = bih1[g * H_ + j0 + jj] + bhh1[g * H_ + j0 + jj];

#pragma unroll 4
        for (int i = tid; i < 4096; i += 256)
            ((uint4*)hsfB)[i] = make_uint4(0u, 0u, 0u, 0u);

        for (int s = 0; s < T_; s++) {
            if (tid < 64) {
                while (ld_acq(&g_flags1[tid * 4]) < (unsigned)(s + 1))
                    __nanosleep(64);
            } else if (tid < 128 && s > 0) {
                while (ld_acq(&g_flags2[(tid - 64) * 4]) < (unsigned)s)
                    __nanosleep(64);
            }
            __syncthreads();
            {
                const uint4* srcA = (const uint4*)g_h1ring[s & 3];
#pragma unroll
                for (int it = 0; it < 16; it++) {
                    int idx = it * 256 + tid;
                    ((uint4*)hsfA)[idx] = __ldcg(srcA + idx);
                }
                if (s > 0) {
                    const uint4* srcB = (const uint4*)g_h2f[(s - 1) & 1];
#pragma unroll
                    for (int it = 0; it < 16; it++) {
                        int idx = it * 256 + tid;
                        ((uint4*)hsfB)[idx] = __ldcg(srcB + idx);
                    }
                }
            }
            __syncthreads();

            float acc[4][4][4];
#pragma unroll
            for (int mt = 0; mt < 4; mt++)
#pragma unroll
                for (int nt = 0; nt < 4; nt++)
#pragma unroll
                    for (int i = 0; i < 4; i++) acc[mt][nt][i] = 0.f;

            const uint32_t* src = isH1 ? hsfA : hsfB;
#pragma unroll
            for (int ktl = 0; ktl < 8; ktl++) {
                int kt = wq * 8 + ktl;
#pragma unroll
                for (int mt = 0; mt < 4; mt++) {
                    uint4 av = *(const uint4*)&src[(((mt * 32 + kt) * 32) + lane) * 4];
                    uint32_t a[4] = {av.x, av.y, av.z, av.w};
#pragma unroll
                    for (int nt = 0; nt < 4; nt++)
                        mma_f16(acc[mt][nt], a, bfr[nt][ktl]);
                }
            }

#pragma unroll
            for (int mt = 0; mt < 4; mt++)
#pragma unroll
                for (int nt = 0; nt < 4; nt++)
                    *(float4*)&red[(((w * 4 + mt) * 4 + nt) << 7) + lane * 4] =
                        make_float4(acc[mt][nt][0], acc[mt][nt][1],
                                    acc[mt][nt][2], acc[mt][nt][3]);
            __syncthreads();

            __half* ring = g_h2f[s & 1];
#pragma unroll
            for (int half = 0; half < 2; half++) {
                int b     = bq + half * 32;
                int row_t = b & 15;
                int mt    = b >> 4;
                int pos   = (((row_t & 7) * 4 + (jj >> 1)) << 2) + (jj & 1) +
                            ((row_t >> 3) << 1);
                float gv[4];
#pragma unroll
                for (int g = 0; g < 4; g++) {
                    float sacc = bs[g];
#pragma unroll
                    for (int ww = 0; ww < 8; ww++)
                        sacc += red[(((ww * 4 + mt) * 4 + g) << 7) + pos];
                    gv[g] = sacc;
                }
                float ig = 1.f / (1.f + __expf(-gv[0]));
                float fg = 1.f / (1.f + __expf(-gv[1]));
                float gg = tanhf(gv[2]);
                float og = 1.f / (1.f + __expf(-gv[3]));
                float cold = half ? creg1 : creg0;
                float cn = fg * cold + ig * gg;
                if (half) creg1 = cn; else creg0 = cn;
                float hn = og * tanhf(cn);
                __half hb = __float2half_rn(hn);
                st_hfrag(ring, b, j0 + jj, hb);
                hseq[(size_t)(b * T_ + s) * H_ + j0 + jj] = hb;
            }

            __syncthreads();
            if (tid == 0) st_rel(&g_flags2[bid2 * 4], (unsigned)(s + 1));
        }
    }
}

// ---------------------------------------------------------------------------
extern "C" void kernel_launch(void* const* d_in, const int* in_sizes, int n_in,
                              void* d_out, int out_size) {
    (void)in_sizes; (void)n_in; (void)out_size;
    const int*   sentence = (const int*)d_in[0];
    const float* features = (const float*)d_in[1];
    const float* emb   = (const float*)d_in[3];
    const float* W_ih0 = (const float*)d_in[4];
    const float* W_hh0 = (const float*)d_in[5];
    const float* b_ih0 = (const float*)d_in[6];
    const float* b_hh0 = (const float*)d_in[7];
    const float* W_ih1 = (const float*)d_in[8];
    const float* W_hh1 = (const float*)d_in[9];
    const float* b_ih1 = (const float*)d_in[10];
    const float* b_hh1 = (const float*)d_in[11];
    const float* fc_W  = (const float*)d_in[12];
    const float* fc_b  = (const float*)d_in[13];
    float* out = (float*)d_out;

    float *xp;
    __half *x0, *hseq, *wih0, *wih1, *fcw;
    cudaGetSymbolAddress((void**)&x0, g_x0);
    cudaGetSymbolAddress((void**)&xp, g_xp);
    cudaGetSymbolAddress((void**)&hseq, g_hseq);
    cudaGetSymbolAddress((void**)&wih0, g_wih0);
    cudaGetSymbolAddress((void**)&wih1, g_wih1);
    cudaGetSymbolAddress((void**)&fcw, g_fcw);

    cudaFuncSetAttribute(lstm_wave,
                         cudaFuncAttributeMaxDynamicSharedMemorySize, 196608);
    cudaFuncSetAttribute(gemm2h<0>,
                         cudaFuncAttributeMaxDynamicSharedMemorySize, 4 * HSTG);
    cudaFuncSetAttribute(gemm2h<1>,
                         cudaFuncAttributeMaxDynamicSharedMemorySize, 4 * HSTG);

    to_half<<<(G4_ * E_ / 4 + 255) / 256, 256>>>(W_ih0, wih0, G4_ * E_ / 4);
    to_half<<<(G4_ * H_ / 4 + 255) / 256, 256>>>(W_ih1, wih1, G4_ * H_ / 4);
    to_half<<<(V_ * H_ / 4 + 255) / 256, 256>>>(fc_W, fcw, V_ * H_ / 4);

    build_x0<<<(M_ * (E_ / 4) + 255) / 256, 256>>>(sentence, features, emb, x0);

    gemm2h<0><<<dim3(G4_ / 128, M_ / 128), 256, 4 * HSTG>>>(
        x0, wih0, b_ih0, b_hh0, xp, M_, G4_, E_);

    reset_bar<<<1, 256>>>();
    lstm_wave<<<128, 256, 196608>>>(xp, W_hh0, wih1, W_hh1, b_ih1, b_hh1, hseq);

    gemm2h<1><<<dim3(V_ / 128, M_ / 128), 256, 4 * HSTG>>>(
        hseq, fcw, fc_b, nullptr, out, M_, V_, H_);
}

// round 10
// speedup vs baseline: 1.7882x; 1.0063x over previous
#include <cuda_runtime.h>
#include <cuda_fp16.h>
#include <cstdint>

// ---------------------------------------------------------------------------
// Decoder: emb gather + concat -> fused [wavefront LSTM x2 + FC drain]
// B=64, T=32, E=H=512, V=32000.
// One persistent kernel: blocks 0-127 = wave (2 LSTM layers, 1-step skew),
// blocks 128-147 = FC workers from t=0; wave blocks join the FC pool after
// their 32 steps. FC tiles (16b x 8t x 256v) gated on layer-2 progress.
// ---------------------------------------------------------------------------
#define B_  64
#define T_  32
#define E_  512
#define H_  512
#define V_  32000
#define M_  (B_ * T_)    // 2048
#define G4_ (4 * H_)     // 2048
#define NFCT 2000        // FC tiles: 4 tgroups x 4 btiles x 125 ntiles

__device__ __half   g_x0[M_ * E_];
__device__ float    g_xp[M_ * G4_];
__device__ __half   g_hseq[M_ * H_];
__device__ __half   g_wih0[G4_ * E_];
__device__ __half   g_wih1[G4_ * H_];
__device__ __half   g_fcw[V_ * H_];
__device__ __align__(16) __half g_h1ring[4][B_ * H_];
__device__ __align__(16) __half g_h2f[2][B_ * H_];
__device__ unsigned g_flags1[64 * 4];
__device__ unsigned g_flags2[64 * 4];
__device__ unsigned g_ticket;

// ---------------------------------------------------------------------------
__device__ __forceinline__ uint32_t packh2(float a, float b) {
    __half2 h = __floats2half2_rn(a, b);
    return *(uint32_t*)&h;
}

__device__ __forceinline__ void mma_f16(float (&c)[4], const uint32_t (&a)[4],
                                        const uint32_t (&b)[2]) {
    asm volatile(
        "mma.sync.aligned.m16n8k16.row.col.f32.f16.f16.f32 "
        "{%0,%1,%2,%3}, {%4,%5,%6,%7}, {%8,%9}, {%0,%1,%2,%3};\n"
        : "+f"(c[0]), "+f"(c[1]), "+f"(c[2]), "+f"(c[3])
        : "r"(a[0]), "r"(a[1]), "r"(a[2]), "r"(a[3]), "r"(b[0]), "r"(b[1]));
}

__device__ __forceinline__ void st_rel(unsigned* p, unsigned v) {
    asm volatile("st.release.gpu.global.u32 [%0], %1;" :: "l"(p), "r"(v)
                 : "memory");
}
__device__ __forceinline__ unsigned ld_acq(unsigned* p) {
    unsigned v;
    asm volatile("ld.acquire.gpu.global.u32 %0, [%1];" : "=r"(v) : "l"(p)
                 : "memory");
    return v;
}

__device__ __forceinline__ uint32_t smem_u32(const void* p) {
    uint32_t a;
    asm("{ .reg .u64 t; cvta.to.shared.u64 t, %1; cvt.u32.u64 %0, t; }"
        : "=r"(a) : "l"(p));
    return a;
}

__device__ __forceinline__ void cp16(uint32_t dst, const void* src) {
    asm volatile("cp.async.cg.shared.global [%0], [%1], 16;\n"
                 :: "r"(dst), "l"(src));
}

// m16n8k16 A-fragment-layout store (h ring buffers)
__device__ __forceinline__ void st_hfrag(__half* base, int b, int j, __half h) {
    int mt     = b >> 4;
    int kt     = j >> 4;
    int lane_t = (b & 7) * 4 + ((j >> 1) & 3);
    int q      = ((b >> 3) & 1) | (((j >> 3) & 1) << 1);
    base[(((mt * 32 + kt) * 32 + lane_t) << 3) + (q << 1) + (j & 1)] = h;
}

// ---------------------------------------------------------------------------
__global__ void to_half(const float* __restrict__ src, __half* __restrict__ dst,
                        int n4) {
    int i = blockIdx.x * blockDim.x + threadIdx.x;
    if (i >= n4) return;
    float4 v = *(const float4*)(src + (size_t)i * 4);
    uint2 u;
    u.x = packh2(v.x, v.y);
    u.y = packh2(v.z, v.w);
    *(uint2*)(dst + (size_t)i * 4) = u;
}

__global__ void build_x0(const int* __restrict__ sentence,
                         const float* __restrict__ features,
                         const float* __restrict__ emb,
                         __half* __restrict__ x0) {
    int i4 = blockIdx.x * blockDim.x + threadIdx.x;
    if (i4 >= M_ * (E_ / 4)) return;
    int m  = i4 >> 7;
    int e4 = (i4 & 127) * 4;
    int b  = m >> 5;
    int t  = m & 31;
    float4 v;
    if (t == 0) {
        v = *(const float4*)&features[b * E_ + e4];
    } else {
        int tok = sentence[b * T_ + (t - 1)];
        v = *(const float4*)&emb[tok * E_ + e4];
    }
    uint2 u;
    u.x = packh2(v.x, v.y);
    u.y = packh2(v.z, v.w);
    *(uint2*)(x0 + (size_t)m * E_ + e4) = u;
}

__global__ void reset_bar() {
    int i = threadIdx.x;
    if (i < 256) { g_flags1[i] = 0; g_flags2[i] = 0; }
    if (i == 0) g_ticket = 0;
}

// ---------------------------------------------------------------------------
// fp16 GEMM for the layer-0 input projection (round-9 proven config):
// BM=128 BN=128 BK=32, 4-stage cp.async, warp tile 64x32, K=512.
// ---------------------------------------------------------------------------
#define HLDW 20
#define PSTG ((128 + 128) * HLDW * 4)

__global__ void __launch_bounds__(256, 2)
gemm_proj(const __half* __restrict__ A, const __half* __restrict__ Bm,
          const float* __restrict__ bias1, const float* __restrict__ bias2,
          float* __restrict__ C, int M, int N, int K) {
    extern __shared__ uint8_t dsm[];
    const uint32_t base = smem_u32(dsm);

    const int tid  = threadIdx.x;
    const int lane = tid & 31;
    const int warp = tid >> 5;
    const int wm = (warp & 1) * 64;
    const int wn = (warp >> 1) * 32;
    const int m0 = blockIdx.y * 128;
    const int n0 = blockIdx.x * 128;

    float acc[4][4][4];
#pragma unroll
    for (int mt = 0; mt < 4; mt++)
#pragma unroll
        for (int nt = 0; nt < 4; nt++)
#pragma unroll
            for (int i = 0; i < 4; i++) acc[mt][nt][i] = 0.f;

    auto issue = [&](int s) {
        uint32_t sa = base + (s & 3) * PSTG;
        uint32_t sb = sa + 128 * HLDW * 4;
        const __half* ap = A + (size_t)m0 * K + s * 32;
        const __half* wp = Bm + (size_t)n0 * K + s * 32;
#pragma unroll
        for (int i = 0; i < 2; i++) {
            int c = i * 256 + tid;
            int row = c >> 2, kk = c & 3;
            cp16(sa + (uint32_t)(row * 80 + kk * 16),
                 ap + (size_t)row * K + kk * 8);
        }
#pragma unroll
        for (int i = 0; i < 2; i++) {
            int c = i * 256 + tid;
            int row = c >> 2, kk = c & 3;
            cp16(sb + (uint32_t)(row * 80 + kk * 16),
                 wp + (size_t)row * K + kk * 8);
        }
    };

#pragma unroll
    for (int s = 0; s < 3; s++) {
        issue(s);
        asm volatile("cp.async.commit_group;" ::: "memory");
    }

    for (int k = 0; k < 16; k++) {
        if (k <= 13)      asm volatile("cp.async.wait_group 2;" ::: "memory");
        else if (k == 14) asm volatile("cp.async.wait_group 1;" ::: "memory");
        else              asm volatile("cp.async.wait_group 0;" ::: "memory");
        __syncthreads();
        if (k + 3 < 16) {
            issue(k + 3);
            asm volatile("cp.async.commit_group;" ::: "memory");
        }

        const uint32_t* As = (const uint32_t*)(dsm + (size_t)(k & 3) * PSTG);
        const uint32_t* Bs = As + 128 * HLDW;
#pragma unroll
        for (int ks = 0; ks < 2; ks++) {
            int kc = ks * 8 + (lane & 3);
            uint32_t bf[4][2];
#pragma unroll
            for (int nt = 0; nt < 4; nt++) {
                int nr = wn + nt * 8 + (lane >> 2);
                bf[nt][0] = Bs[nr * HLDW + kc];
                bf[nt][1] = Bs[nr * HLDW + kc + 4];
            }
#pragma unroll
            for (int mt = 0; mt < 4; mt++) {
                int r = wm + mt * 16 + (lane >> 2);
                uint32_t af[4];
                af[0] = As[r * HLDW + kc];
                af[1] = As[(r + 8) * HLDW + kc];
                af[2] = As[r * HLDW + kc + 4];
                af[3] = As[(r + 8) * HLDW + kc + 4];
#pragma unroll
                for (int nt = 0; nt < 4; nt++)
                    mma_f16(acc[mt][nt], af, bf[nt]);
            }
        }
    }

#pragma unroll
    for (int nt = 0; nt < 4; nt++) {
        int cn  = n0 + wn + nt * 8 + (lane & 3) * 2;
        float bv0 = bias1[cn] + bias2[cn];
        float bv1 = bias1[cn + 1] + bias2[cn + 1];
#pragma unroll
        for (int mt = 0; mt < 4; mt++) {
            int r = m0 + wm + mt * 16 + (lane >> 2);
            C[(size_t)r * N + cn]           = acc[mt][nt][0] + bv0;
            C[(size_t)r * N + cn + 1]       = acc[mt][nt][1] + bv1;
            C[(size_t)(r + 8) * N + cn]     = acc[mt][nt][2] + bv0;
            C[(size_t)(r + 8) * N + cn + 1] = acc[mt][nt][3] + bv1;
        }
    }
}

// ---------------------------------------------------------------------------
// Fused wave + FC kernel. Grid 148 blocks x 256 threads, 192KB smem.
// Blocks 0-63: LSTM layer 1. Blocks 64-127: LSTM layer 2 (fused input proj).
// Blocks 128-147: FC workers from launch. Wave blocks join FC pool after T_.
// FC tile: M=128 (16 b x 8 t), N=256, K=512; 4-stage cp.async; warp 64x64.
// Tile w: g=w/500 (t-group), u=w%500: b0=(u/125)*16, n0=(u%125)*256, t0=8g.
// Gate: all 64 layer-2 flags >= 8(g+1).
// ---------------------------------------------------------------------------
#define FSTG ((128 + 256) * HLDW * 4)   // 30720 B/stage, x4 = 122880

__global__ void __launch_bounds__(256, 1)
wave_fc(const float* __restrict__ xp0, const float* __restrict__ Whh0,
        const __half* __restrict__ wih1, const float* __restrict__ Whh1,
        const float* __restrict__ bih1, const float* __restrict__ bhh1,
        __half* __restrict__ hseq,
        const __half* __restrict__ fcw, const float* __restrict__ fcb,
        float* __restrict__ out) {
    extern __shared__ uint32_t smu[];
    __shared__ int s_w;
    const int tid  = threadIdx.x;
    const int lane = tid & 31;
    const int w    = tid >> 5;
    const int gid  = lane >> 2;
    const int tig  = lane & 3;
    const int jj   = tid & 7;
    const int bq   = tid >> 3;
    float creg0 = 0.f, creg1 = 0.f;

    if (blockIdx.x < 64) {
        // ================= layer 1 =================
        uint32_t* hsf = smu;
        float*    red = (float*)(smu + 16384);
        const int j0 = blockIdx.x * 8;

        uint32_t bfr[4][4][2];
#pragma unroll
        for (int nt = 0; nt < 4; nt++)
#pragma unroll
            for (int ktl = 0; ktl < 4; ktl++) {
                int n  = nt * H_ + j0 + gid;
                int kb = w * 64 + ktl * 16 + tig * 2;
                const float* wr = Whh0 + (size_t)n * H_;
                bfr[nt][ktl][0] = packh2(wr[kb],     wr[kb + 1]);
                bfr[nt][ktl][1] = packh2(wr[kb + 8], wr[kb + 9]);
            }

#pragma unroll 4
        for (int i = tid; i < 4096; i += 256)
            ((uint4*)hsf)[i] = make_uint4(0u, 0u, 0u, 0u);

        for (int t = 0; t < T_; t++) {
            float xpr[2][4];
#pragma unroll
            for (int half = 0; half < 2; half++) {
                int b = bq + half * 32;
#pragma unroll
                for (int g = 0; g < 4; g++)
                    xpr[half][g] =
                        xp0[(size_t)(b * T_ + t) * G4_ + g * H_ + j0 + jj];
            }

            if (t > 0) {
                if (tid < 64) {
                    while (ld_acq(&g_flags1[tid * 4]) < (unsigned)t)
                        __nanosleep(64);
                } else if (tid < 128 && t >= 4) {
                    while (ld_acq(&g_flags2[(tid - 64) * 4]) < (unsigned)(t - 3))
                        __nanosleep(64);
                }
                __syncthreads();
                const uint4* src = (const uint4*)g_h1ring[(t - 1) & 3];
#pragma unroll
                for (int it = 0; it < 16; it++) {
                    int idx = it * 256 + tid;
                    ((uint4*)hsf)[idx] = __ldcg(src + idx);
                }
            }
            __syncthreads();

            float acc[4][4][4];
#pragma unroll
            for (int mt = 0; mt < 4; mt++)
#pragma unroll
                for (int nt = 0; nt < 4; nt++)
#pragma unroll
                    for (int i = 0; i < 4; i++) acc[mt][nt][i] = 0.f;

#pragma unroll
            for (int ktl = 0; ktl < 4; ktl++) {
                int kt = w * 4 + ktl;
#pragma unroll
                for (int mt = 0; mt < 4; mt++) {
                    uint4 av = *(const uint4*)&hsf[(((mt * 32 + kt) * 32) + lane) * 4];
                    uint32_t a[4] = {av.x, av.y, av.z, av.w};
#pragma unroll
                    for (int nt = 0; nt < 4; nt++)
                        mma_f16(acc[mt][nt], a, bfr[nt][ktl]);
                }
            }

#pragma unroll
            for (int mt = 0; mt < 4; mt++)
#pragma unroll
                for (int nt = 0; nt < 4; nt++)
                    *(float4*)&red[(((w * 4 + mt) * 4 + nt) << 7) + lane * 4] =
                        make_float4(acc[mt][nt][0], acc[mt][nt][1],
                                    acc[mt][nt][2], acc[mt][nt][3]);
            __syncthreads();

            __half* ring = g_h1ring[t & 3];
#pragma unroll
            for (int half = 0; half < 2; half++) {
                int b     = bq + half * 32;
                int row_t = b & 15;
                int mt    = b >> 4;
                int pos   = (((row_t & 7) * 4 + (jj >> 1)) << 2) + (jj & 1) +
                            ((row_t >> 3) << 1);
                float gv[4];
#pragma unroll
                for (int g = 0; g < 4; g++) {
                    float s = xpr[half][g];
#pragma unroll
                    for (int ww = 0; ww < 8; ww++)
                        s += red[(((ww * 4 + mt) * 4 + g) << 7) + pos];
                    gv[g] = s;
                }
                float ig = 1.f / (1.f + __expf(-gv[0]));
                float fg = 1.f / (1.f + __expf(-gv[1]));
                float gg = tanhf(gv[2]);
                float og = 1.f / (1.f + __expf(-gv[3]));
                float cold = half ? creg1 : creg0;
                float cn = fg * cold + ig * gg;
                if (half) creg1 = cn; else creg0 = cn;
                float hn = og * tanhf(cn);
                st_hfrag(ring, b, j0 + jj, __float2half_rn(hn));
            }

            __syncthreads();
            if (tid == 0) st_rel(&g_flags1[blockIdx.x * 4], (unsigned)(t + 1));
        }
    } else if (blockIdx.x < 128) {
        // ================= layer 2 (fused input projection) =================
        uint32_t* hsfA = smu;
        uint32_t* hsfB = smu + 16384;
        float*    red  = (float*)(smu + 32768);
        const int bid2 = blockIdx.x - 64;
        const int j0 = bid2 * 8;
        const int wq = w & 3;
        const bool isH1 = (w < 4);

        uint32_t bfr[4][8][2];
#pragma unroll
        for (int nt = 0; nt < 4; nt++)
#pragma unroll
            for (int ktl = 0; ktl < 8; ktl++) {
                int n  = nt * H_ + j0 + gid;
                int kb = wq * 128 + ktl * 16 + tig * 2;
                if (isH1) {
                    bfr[nt][ktl][0] = *(const uint32_t*)&wih1[(size_t)n * H_ + kb];
                    bfr[nt][ktl][1] = *(const uint32_t*)&wih1[(size_t)n * H_ + kb + 8];
                } else {
                    const float* wr = Whh1 + (size_t)n * H_;
                    bfr[nt][ktl][0] = packh2(wr[kb],     wr[kb + 1]);
                    bfr[nt][ktl][1] = packh2(wr[kb + 8], wr[kb + 9]);
                }
            }

        float bs[4];
#pragma unroll
        for (int g = 0; g < 4; g++)
            bs[g] = bih1[g * H_ + j0 + jj] + bhh1[g * H_ + j0 + jj];

#pragma unroll 4
        for (int i = tid; i < 4096; i += 256)
            ((uint4*)hsfB)[i] = make_uint4(0u, 0u, 0u, 0u);

        for (int s = 0; s < T_; s++) {
            if (tid < 64) {
                while (ld_acq(&g_flags1[tid * 4]) < (unsigned)(s + 1))
                    __nanosleep(64);
            } else if (tid < 128 && s > 0) {
                while (ld_acq(&g_flags2[(tid - 64) * 4]) < (unsigned)s)
                    __nanosleep(64);
            }
            __syncthreads();
            {
                const uint4* srcA = (const uint4*)g_h1ring[s & 3];
#pragma unroll
                for (int it = 0; it < 16; it++) {
                    int idx = it * 256 + tid;
                    ((uint4*)hsfA)[idx] = __ldcg(srcA + idx);
                }
                if (s > 0) {
                    const uint4* srcB = (const uint4*)g_h2f[(s - 1) & 1];
#pragma unroll
                    for (int it = 0; it < 16; it++) {
                        int idx = it * 256 + tid;
                        ((uint4*)hsfB)[idx] = __ldcg(srcB + idx);
                    }
                }
            }
            __syncthreads();

            float acc[4][4][4];
#pragma unroll
            for (int mt = 0; mt < 4; mt++)
#pragma unroll
                for (int nt = 0; nt < 4; nt++)
#pragma unroll
                    for (int i = 0; i < 4; i++) acc[mt][nt][i] = 0.f;

            const uint32_t* src = isH1 ? hsfA : hsfB;
#pragma unroll
            for (int ktl = 0; ktl < 8; ktl++) {
                int kt = wq * 8 + ktl;
#pragma unroll
                for (int mt = 0; mt < 4; mt++) {
                    uint4 av = *(const uint4*)&src[(((mt * 32 + kt) * 32) + lane) * 4];
                    uint32_t a[4] = {av.x, av.y, av.z, av.w};
#pragma unroll
                    for (int nt = 0; nt < 4; nt++)
                        mma_f16(acc[mt][nt], a, bfr[nt][ktl]);
                }
            }

#pragma unroll
            for (int mt = 0; mt < 4; mt++)
#pragma unroll
                for (int nt = 0; nt < 4; nt++)
                    *(float4*)&red[(((w * 4 + mt) * 4 + nt) << 7) + lane * 4] =
                        make_float4(acc[mt][nt][0], acc[mt][nt][1],
                                    acc[mt][nt][2], acc[mt][nt][3]);
            __syncthreads();

            __half* ring = g_h2f[s & 1];
#pragma unroll
            for (int half = 0; half < 2; half++) {
                int b     = bq + half * 32;
                int row_t = b & 15;
                int mt    = b >> 4;
                int pos   = (((row_t & 7) * 4 + (jj >> 1)) << 2) + (jj & 1) +
                            ((row_t >> 3) << 1);
                float gv[4];
#pragma unroll
                for (int g = 0; g < 4; g++) {
                    float sacc = bs[g];
#pragma unroll
                    for (int ww = 0; ww < 8; ww++)
                        sacc += red[(((ww * 4 + mt) * 4 + g) << 7) + pos];
                    gv[g] = sacc;
                }
                float ig = 1.f / (1.f + __expf(-gv[0]));
                float fg = 1.f / (1.f + __expf(-gv[1]));
                float gg = tanhf(gv[2]);
                float og = 1.f / (1.f + __expf(-gv[3]));
                float cold = half ? creg1 : creg0;
                float cn = fg * cold + ig * gg;
                if (half) creg1 = cn; else creg0 = cn;
                float hn = og * tanhf(cn);
                __half hb = __float2half_rn(hn);
                st_hfrag(ring, b, j0 + jj, hb);
                hseq[(size_t)(b * T_ + s) * H_ + j0 + jj] = hb;
            }

            __syncthreads();
            if (tid == 0) st_rel(&g_flags2[bid2 * 4], (unsigned)(s + 1));
        }
    }

    // ===================== FC worker pool =====================
    {
        uint8_t* dsm = (uint8_t*)smu;
        const uint32_t base = smem_u32(dsm);
        const int wm = (w & 1) * 64;
        const int wn = (w >> 1) * 64;

        while (true) {
            __syncthreads();
            if (tid == 0) s_w = atomicAdd(&g_ticket, 1);
            __syncthreads();
            int tw = s_w;
            if (tw >= NFCT) break;

            int g  = tw / 500;
            int u  = tw % 500;
            int b0 = (u / 125) * 16;
            int n0 = (u % 125) * 256;
            int t0 = g * 8;

            // gate: hseq steps t0..t0+7 complete in all 64 layer-2 blocks
            if (tid < 64) {
                unsigned need = (unsigned)(8 * (g + 1));
                while (ld_acq(&g_flags2[tid * 4]) < need) __nanosleep(128);
            }
            __syncthreads();

            float acc[4][8][4];
#pragma unroll
            for (int mt = 0; mt < 4; mt++)
#pragma unroll
                for (int nt = 0; nt < 8; nt++)
#pragma unroll
                    for (int i = 0; i < 4; i++) acc[mt][nt][i] = 0.f;

            auto issue = [&](int s) {
                uint32_t sa = base + (s & 3) * FSTG;
                uint32_t sb = sa + 128 * HLDW * 4;
#pragma unroll
                for (int i = 0; i < 2; i++) {   // A: 128 rows x 4 chunks
                    int c = i * 256 + tid;
                    int row = c >> 2, kk = c & 3;
                    int m = (b0 + (row >> 3)) * T_ + t0 + (row & 7);
                    cp16(sa + (uint32_t)(row * 80 + kk * 16),
                         hseq + (size_t)m * H_ + s * 32 + kk * 8);
                }
#pragma unroll
                for (int i = 0; i < 4; i++) {   // B: 256 rows x 4 chunks
                    int c = i * 256 + tid;
                    int row = c >> 2, kk = c & 3;
                    cp16(sb + (uint32_t)(row * 80 + kk * 16),
                         fcw + (size_t)(n0 + row) * H_ + s * 32 + kk * 8);
                }
            };

#pragma unroll
            for (int s = 0; s < 3; s++) {
                issue(s);
                asm volatile("cp.async.commit_group;" ::: "memory");
            }

            for (int k = 0; k < 16; k++) {
                if (k <= 13)      asm volatile("cp.async.wait_group 2;" ::: "memory");
                else if (k == 14) asm volatile("cp.async.wait_group 1;" ::: "memory");
                else              asm volatile("cp.async.wait_group 0;" ::: "memory");
                __syncthreads();
                if (k + 3 < 16) {
                    issue(k + 3);
                    asm volatile("cp.async.commit_group;" ::: "memory");
                }

                const uint32_t* As = (const uint32_t*)(dsm + (size_t)(k & 3) * FSTG);
                const uint32_t* Bs = As + 128 * HLDW;
#pragma unroll
                for (int ks = 0; ks < 2; ks++) {
                    int kc = ks * 8 + (lane & 3);
                    uint32_t bf[8][2];
#pragma unroll
                    for (int nt = 0; nt < 8; nt++) {
                        int nr = wn + nt * 8 + (lane >> 2);
                        bf[nt][0] = Bs[nr * HLDW + kc];
                        bf[nt][1] = Bs[nr * HLDW + kc + 4];
                    }
#pragma unroll
                    for (int mt = 0; mt < 4; mt++) {
                        int r = wm + mt * 16 + (lane >> 2);
                        uint32_t af[4];
                        af[0] = As[r * HLDW + kc];
                        af[1] = As[(r + 8) * HLDW + kc];
                        af[2] = As[r * HLDW + kc + 4];
                        af[3] = As[(r + 8) * HLDW + kc + 4];
#pragma unroll
                        for (int nt = 0; nt < 8; nt++)
                            mma_f16(acc[mt][nt], af, bf[nt]);
                    }
                }
            }

            // epilogue: out[b, v, t], row r -> b = b0 + r/8, t = t0 + r%8
#pragma unroll
            for (int nt = 0; nt < 8; nt++) {
                int cn  = n0 + wn + nt * 8 + (lane & 3) * 2;
                float bv0 = fcb[cn];
                float bv1 = fcb[cn + 1];
#pragma unroll
                for (int mt = 0; mt < 4; mt++) {
                    int r  = wm + mt * 16 + (lane >> 2);
                    int b1 = b0 + (r >> 3),       t1 = t0 + (r & 7);
                    int b2 = b0 + ((r + 8) >> 3), t2 = t0 + ((r + 8) & 7);
                    size_t base1 = (size_t)b1 * V_ * T_ + t1;
                    size_t base2 = (size_t)b2 * V_ * T_ + t2;
                    out[base1 + (size_t)cn * T_]       = acc[mt][nt][0] + bv0;
                    out[base1 + (size_t)(cn + 1) * T_] = acc[mt][nt][1] + bv1;
                    out[base2 + (size_t)cn * T_]       = acc[mt][nt][2] + bv0;
                    out[base2 + (size_t)(cn + 1) * T_] = acc[mt][nt][3] + bv1;
                }
            }
        }
    }
}

// ---------------------------------------------------------------------------
extern "C" void kernel_launch(void* const* d_in, const int* in_sizes, int n_in,
                              void* d_out, int out_size) {
    (void)in_sizes; (void)n_in; (void)out_size;
    const int*   sentence = (const int*)d_in[0];
    const float* features = (const float*)d_in[1];
    const float* emb   = (const float*)d_in[3];
    const float* W_ih0 = (const float*)d_in[4];
    const float* W_hh0 = (const float*)d_in[5];
    const float* b_ih0 = (const float*)d_in[6];
    const float* b_hh0 = (const float*)d_in[7];
    const float* W_ih1 = (const float*)d_in[8];
    const float* W_hh1 = (const float*)d_in[9];
    const float* b_ih1 = (const float*)d_in[10];
    const float* b_hh1 = (const float*)d_in[11];
    const float* fc_W  = (const float*)d_in[12];
    const float* fc_b  = (const float*)d_in[13];
    float* out = (float*)d_out;

    float *xp;
    __half *x0, *hseq, *wih0, *wih1, *fcw;
    cudaGetSymbolAddress((void**)&x0, g_x0);
    cudaGetSymbolAddress((void**)&xp, g_xp);
    cudaGetSymbolAddress((void**)&hseq, g_hseq);
    cudaGetSymbolAddress((void**)&wih0, g_wih0);
    cudaGetSymbolAddress((void**)&wih1, g_wih1);
    cudaGetSymbolAddress((void**)&fcw, g_fcw);

    cudaFuncSetAttribute(wave_fc,
                         cudaFuncAttributeMaxDynamicSharedMemorySize, 196608);
    cudaFuncSetAttribute(gemm_proj,
                         cudaFuncAttributeMaxDynamicSharedMemorySize, 4 * PSTG);

    to_half<<<(G4_ * E_ / 4 + 255) / 256, 256>>>(W_ih0, wih0, G4_ * E_ / 4);
    to_half<<<(G4_ * H_ / 4 + 255) / 256, 256>>>(W_ih1, wih1, G4_ * H_ / 4);
    to_half<<<(V_ * H_ / 4 + 255) / 256, 256>>>(fc_W, fcw, V_ * H_ / 4);

    build_x0<<<(M_ * (E_ / 4) + 255) / 256, 256>>>(sentence, features, emb, x0);

    gemm_proj<<<dim3(G4_ / 128, M_ / 128), 256, 4 * PSTG>>>(
        x0, wih0, b_ih0, b_hh0, xp, M_, G4_, E_);

    reset_bar<<<1, 256>>>();
    wave_fc<<<148, 256, 196608>>>(xp, W_hh0, wih1, W_hh1, b_ih1, b_hh1,
                                  hseq, fcw, fc_b, out);
}